// round 10
// baseline (speedup 1.0000x reference)
#include <cuda_runtime.h>
#include <cuda_bf16.h>
#include <cuda_fp16.h>
#include <cstdint>

#define NA 4096
#define NB 4096
#define DD 256
#define HH 4
#define DKK 64
#define BM 128
#define BC 64
#define NT (NB / BC)

// ---------------- device scratch ----------------
__device__ __half g_Qhi[HH * NA * DKK];
__device__ __half g_Qlo[HH * NA * DKK];
__device__ __half g_Kh[HH * NB * DKK];
__device__ __half g_Vth[HH * DKK * NB];          // [h][dk][token]
__device__ __half g_wm[(size_t)NA * NB];         // fp16: san(weight) + (mask?0:-1e4)
__device__ float g_ctx[HH * NA * DKK];
__device__ int g_mask_kind;

// ---------------- helpers ----------------
__device__ __forceinline__ uint32_t smem_u32(const void* p) {
    uint32_t a;
    asm("{ .reg .u64 t; cvta.to.shared.u64 t, %1; cvt.u32.u64 %0, t; }" : "=r"(a) : "l"(p));
    return a;
}
__device__ __forceinline__ uint32_t sw128(uint32_t o) { return o ^ ((o >> 3) & 0x70); }

#define CP_ASYNC16(dst, src) \
    asm volatile("cp.async.cg.shared.global [%0], [%1], 16;\n" :: "r"(dst), "l"(src))
#define CP_COMMIT()  asm volatile("cp.async.commit_group;\n" ::: "memory")
#define CP_WAITG(n)  asm volatile("cp.async.wait_group %0;\n" :: "n"(n) : "memory")

#define LDSM4(r0, r1, r2, r3, a) \
    asm volatile("ldmatrix.sync.aligned.m8n8.x4.shared.b16 {%0,%1,%2,%3}, [%4];" \
                 : "=r"(r0), "=r"(r1), "=r"(r2), "=r"(r3) : "r"(a))

__device__ __forceinline__ void mma_f16(float* c, const unsigned* a, const unsigned* b) {
    asm volatile(
        "mma.sync.aligned.m16n8k16.row.col.f32.f16.f16.f32 "
        "{%0,%1,%2,%3}, {%4,%5,%6,%7}, {%8,%9}, {%0,%1,%2,%3};\n"
        : "+f"(c[0]), "+f"(c[1]), "+f"(c[2]), "+f"(c[3])
        : "r"(a[0]), "r"(a[1]), "r"(a[2]), "r"(a[3]), "r"(b[0]), "r"(b[1]));
}

__device__ __forceinline__ void cvt_pack_h(float x0, float x1, unsigned& hi, unsigned& lo) {
    __half h0 = __float2half_rn(x0), h1 = __float2half_rn(x1);
    __half l0 = __float2half_rn(x0 - __half2float(h0));
    __half l1 = __float2half_rn(x1 - __half2float(h1));
    hi = ((unsigned)__half_as_ushort(h1) << 16) | (unsigned)__half_as_ushort(h0);
    lo = ((unsigned)__half_as_ushort(l1) << 16) | (unsigned)__half_as_ushort(l0);
}
__device__ __forceinline__ unsigned pack_h(float x0, float x1) {
    return ((unsigned)__half_as_ushort(__float2half_rn(x1)) << 16)
         | (unsigned)__half_as_ushort(__float2half_rn(x0));
}

__device__ __forceinline__ float san(float x) {
    if (isnan(x)) return 0.f;
    if (isinf(x)) return x > 0.f ? 1.f : -1.f;
    return x;
}

// ---------------- mask dtype detector ----------------
__global__ void detect_mask_kind(const unsigned int* __restrict__ m) {
    __shared__ int s_i32, s_f32;
    if (threadIdx.x == 0) { s_i32 = 1; s_f32 = 1; }
    __syncthreads();
    int ok_i = 1, ok_f = 1;
    for (int i = threadIdx.x; i < 4096; i += 1024) {
        unsigned v = m[i];
        ok_i &= (v <= 1u);
        ok_f &= (v == 0u || v == 0x3F800000u);
    }
    if (!ok_i) atomicAnd(&s_i32, 0);
    if (!ok_f) atomicAnd(&s_f32, 0);
    __syncthreads();
    if (threadIdx.x == 0) g_mask_kind = s_i32 ? 1 : (s_f32 ? 2 : 0);
}

// ---------------- prep: fold sanitize + mask into fp16 weight ----------------
__global__ void __launch_bounds__(256) prep_wm(const float4* __restrict__ w4,
                                               const void* __restrict__ mraw) {
    const int kind = g_mask_kind;
    const size_t n4 = (size_t)NA * NB / 4;
    size_t i = (size_t)blockIdx.x * 256 + threadIdx.x;
    const size_t stride = (size_t)gridDim.x * 256;
    for (; i < n4; i += stride) {
        float4 w = w4[i];
        w.x = san(w.x); w.y = san(w.y); w.z = san(w.z); w.w = san(w.w);
        int b0, b1, b2, b3;
        if (kind == 1) {
            int4 m = ((const int4*)mraw)[i];
            b0 = m.x != 0; b1 = m.y != 0; b2 = m.z != 0; b3 = m.w != 0;
        } else if (kind == 2) {
            float4 m = ((const float4*)mraw)[i];
            b0 = m.x != 0.f; b1 = m.y != 0.f; b2 = m.z != 0.f; b3 = m.w != 0.f;
        } else {
            uchar4 m = ((const uchar4*)mraw)[i];
            b0 = m.x != 0; b1 = m.y != 0; b2 = m.z != 0; b3 = m.w != 0;
        }
        float ox = w.x + (b0 ? 0.f : -10000.f);
        float oy = w.y + (b1 ? 0.f : -10000.f);
        float oz = w.z + (b2 ? 0.f : -10000.f);
        float ow = w.w + (b3 ? 0.f : -10000.f);
        uint2 pk = make_uint2(pack_h(ox, oy), pack_h(oz, ow));
        *(uint2*)&g_wm[i * 4] = pk;
    }
}

// ---------------- projections: fp16 2-term (X hi/lo, W single) ----------------
#define PJ_XF(s)  ((s) * 32768)
#define PJ_WF(s)  (65536 + (s) * 32768)
#define PJ_XHI 131072
#define PJ_XLO 147456
#define PJ_WH  163840
#define PJ_SMEM 180224
#define VT_PITCH 132

__global__ void __launch_bounds__(256, 1) proj_mma(
    const float* __restrict__ a_z, const float* __restrict__ bv_z,
    const float* __restrict__ Wq, const float* __restrict__ Wk, const float* __restrict__ Wv)
{
    extern __shared__ char sm[];
    const uint32_t smb = smem_u32(sm);
    const int tid = threadIdx.x, wid = tid >> 5, lane = tid & 31;
    const int mat = blockIdx.z;
    const int m0 = blockIdx.x * 128, nb = blockIdx.y * 128;
    const float* X = (mat == 0) ? a_z : bv_z;
    const float* W = (mat == 0) ? Wq : (mat == 1 ? Wk : Wv);

    auto load_chunk = [&](int c) {
        const int s = c & 1;
        for (int i = tid; i < 2048; i += 256) {
            int r = i >> 4, q = i & 15;
            CP_ASYNC16(smb + PJ_XF(s) + r * 256 + q * 16,
                       (const char*)&X[(size_t)(m0 + r) * DD + c * 64] + q * 16);
            CP_ASYNC16(smb + PJ_WF(s) + r * 256 + q * 16,
                       (const char*)&W[(size_t)(nb + r) * DD + c * 64] + q * 16);
        }
    };
    load_chunk(0); CP_COMMIT();
    load_chunk(1); CP_COMMIT();

    float oacc[16][4];
#pragma unroll
    for (int nt = 0; nt < 16; nt++)
#pragma unroll
        for (int e = 0; e < 4; e++) oacc[nt][e] = 0.f;

    const int arow = wid * 16 + (lane & 15);
    const int akb = (lane >> 4) * 16;
    const int brow = (lane & 7) + ((lane >> 4) << 3);
    const int bkb = ((lane >> 3) & 1) * 16;

    for (int c = 0; c < 4; c++) {
        const int s = c & 1;
        CP_WAITG(1);
        __syncthreads();
#pragma unroll
        for (int j = 0; j < 16; j++) {
            int p = tid + j * 256;
            int r = p >> 5, cp2 = p & 31;
            float2 xv = *(const float2*)(sm + PJ_XF(s) + r * 256 + cp2 * 8);
            float2 wv = *(const float2*)(sm + PJ_WF(s) + r * 256 + cp2 * 8);
            unsigned hi, lo;
            cvt_pack_h(san(xv.x), san(xv.y), hi, lo);
            uint32_t off = sw128(r * 128 + cp2 * 4);
            *(uint32_t*)(sm + PJ_XHI + off) = hi;
            *(uint32_t*)(sm + PJ_XLO + off) = lo;
            *(uint32_t*)(sm + PJ_WH + off) = pack_h(wv.x, wv.y);
        }
        __syncthreads();
#pragma unroll
        for (int kc = 0; kc < 4; kc++) {
            unsigned ah[4], al[4];
            uint32_t asw = sw128(arow * 128 + kc * 32 + akb);
            LDSM4(ah[0], ah[1], ah[2], ah[3], smb + PJ_XHI + asw);
            LDSM4(al[0], al[1], al[2], al[3], smb + PJ_XLO + asw);
#pragma unroll
            for (int ng = 0; ng < 8; ng++) {
                unsigned bh[4];
                uint32_t bsw = sw128((ng * 16 + brow) * 128 + kc * 32 + bkb);
                LDSM4(bh[0], bh[1], bh[2], bh[3], smb + PJ_WH + bsw);
                mma_f16(oacc[2 * ng], ah, &bh[0]);
                mma_f16(oacc[2 * ng + 1], ah, &bh[2]);
                mma_f16(oacc[2 * ng], al, &bh[0]);
                mma_f16(oacc[2 * ng + 1], al, &bh[2]);
            }
        }
        __syncthreads();
        if (c + 2 < 4) load_chunk(c + 2);
        CP_COMMIT();
    }

    const int er = wid * 16 + (lane >> 2);
    const int tcol = (lane & 3) * 2;

    if (mat == 2) {
        float* smf = (float*)sm;
#pragma unroll
        for (int nt = 0; nt < 16; nt++)
#pragma unroll
            for (int hf = 0; hf < 2; hf++) {
                int row = er + hf * 8;
                int col = nt * 8 + tcol;
                smf[(col) * VT_PITCH + row] = oacc[nt][2 * hf];
                smf[(col + 1) * VT_PITCH + row] = oacc[nt][2 * hf + 1];
            }
        __syncthreads();
        for (int idx = tid; idx < 128 * 32; idx += 256) {
            int c = idx >> 5, tb = idx & 31;
            const float* src = &smf[c * VT_PITCH + tb * 4];
            unsigned u0 = pack_h(src[0], src[1]);
            unsigned u1 = pack_h(src[2], src[3]);
            int col = nb + c;
            int head = col >> 6, cc = col & 63;
            size_t o = (size_t)(head * DKK + cc) * NB + m0 + tb * 4;
            *(uint2*)&g_Vth[o] = make_uint2(u0, u1);
        }
    } else if (mat == 0) {
#pragma unroll
        for (int nt = 0; nt < 16; nt++)
#pragma unroll
            for (int hf = 0; hf < 2; hf++) {
                int row = m0 + er + hf * 8;
                int col = nb + nt * 8 + tcol;
                int head = col >> 6, cc = col & 63;
                float x0 = oacc[nt][2 * hf] * 0.125f;
                float x1 = oacc[nt][2 * hf + 1] * 0.125f;
                unsigned hi, lo;
                cvt_pack_h(x0, x1, hi, lo);
                size_t o = (size_t)(head * NA + row) * DKK + cc;
                *(unsigned*)&g_Qhi[o] = hi;
                *(unsigned*)&g_Qlo[o] = lo;
            }
    } else {
#pragma unroll
        for (int nt = 0; nt < 16; nt++)
#pragma unroll
            for (int hf = 0; hf < 2; hf++) {
                int row = m0 + er + hf * 8;
                int col = nb + nt * 8 + tcol;
                int head = col >> 6, cc = col & 63;
                unsigned u = pack_h(oacc[nt][2 * hf], oacc[nt][2 * hf + 1]);
                size_t o = (size_t)(head * NA + row) * DKK + cc;
                *(unsigned*)&g_Kh[o] = u;
            }
    }
}

// ---------------- attention smem layout: 3-stage, fp16 wm ----------------
#define WMB 144                              // wm row pitch in bytes (128 data + 16 pad)
#define STG 34816                            // K 8192 + V 8192 + wm 18432
#define OFF_Q 0                              // QHI 16384 + QLO 16384
#define OFF_ST(s)  (32768 + (s) * STG)
#define OFF_K(s)   OFF_ST(s)
#define OFF_V(s)   (OFF_ST(s) + 8192)
#define OFF_WM(s)  (OFF_ST(s) + 16384)
#define OFF_OC 32768
#define OFF_LS 0
#define SMEM_BYTES 137216

__device__ __forceinline__ void load_tiles(uint32_t smb, int tid, int h, int a0, int bt) {
    const int s = bt % 3, b0 = bt * BC;
    {
        int r = tid >> 3, c = tid & 7;       // 512 threads: one K + one V chunk each
        uint32_t sw = sw128(r * 128 + c * 16);
        CP_ASYNC16(smb + OFF_K(s) + sw,
                   (const char*)&g_Kh[((size_t)h * NB + b0 + r) * DKK] + c * 16);
        CP_ASYNC16(smb + OFF_V(s) + sw,
                   (const char*)&g_Vth[((size_t)(h * DKK + r)) * NB + b0] + c * 16);
    }
    for (int i = tid; i < 1024; i += 512) {  // wm fp16: 128 rows x 128B
        int r = i >> 3, c = i & 7;
        CP_ASYNC16(smb + OFF_WM(s) + r * WMB + c * 16,
                   (const char*)&g_wm[(size_t)(a0 + r) * NB + b0] + c * 16);
    }
}

// ---------------- attention mainloop: 512 threads, 1 barrier/tile, end-of-body prefetch ----------------
__global__ void __launch_bounds__(512, 1) attn_kernel() {
    extern __shared__ char sm[];
    const uint32_t smb = smem_u32(sm);
    const int tid = threadIdx.x, wid = tid >> 5, lane = tid & 31;
    const int wg = wid >> 3, wrow = wid & 7;
    const int a0 = blockIdx.x * BM, h = blockIdx.y;

    for (int i = tid; i < 1024; i += 512) {
        int r = i >> 3, c = i & 7;
        uint32_t sw = sw128(r * 128 + c * 16);
        CP_ASYNC16(smb + OFF_Q + sw,
                   (const char*)&g_Qhi[((size_t)h * NA + a0 + r) * DKK] + c * 16);
        CP_ASYNC16(smb + OFF_Q + 16384 + sw,
                   (const char*)&g_Qlo[((size_t)h * NA + a0 + r) * DKK] + c * 16);
    }
    load_tiles(smb, tid, h, a0, 0); CP_COMMIT();   // G1: Q + tile0
    load_tiles(smb, tid, h, a0, 1); CP_COMMIT();   // G2: tile1

    float oacc[8][4];
#pragma unroll
    for (int nt = 0; nt < 8; nt++)
#pragma unroll
        for (int e = 0; e < 4; e++) oacc[nt][e] = 0.f;
    float lsum0 = 0.f, lsum1 = 0.f;

    const int qrow = wrow * 16 + (lane & 15);
    const int qcb = (lane >> 4) * 16;
    const int brow = (lane & 7) + ((lane >> 4) << 3);
    const int bkb = ((lane >> 3) & 1) * 16;
    const int er = wrow * 16 + (lane >> 2);
    const int tcol = (lane & 3) * 2;

    for (int bt = 0; bt < NT; bt++) {
        const int s = bt % 3;
        CP_WAITG(1);            // tile bt's loads complete
        __syncthreads();        // all warps finished tile bt-1's body

        // ---- S(wg half) = Q K^T : (qh+ql)·kh ----
        float sacc[4][4];
#pragma unroll
        for (int nt = 0; nt < 4; nt++)
#pragma unroll
            for (int e = 0; e < 4; e++) sacc[nt][e] = 0.f;

        const uint32_t kbase = smb + OFF_K(s);
#pragma unroll
        for (int kc = 0; kc < 4; kc++) {
            unsigned qh[4], ql[4];
            uint32_t qsw = sw128(qrow * 128 + kc * 32 + qcb);
            LDSM4(qh[0], qh[1], qh[2], qh[3], smb + OFF_Q + qsw);
            LDSM4(ql[0], ql[1], ql[2], ql[3], smb + OFF_Q + 16384 + qsw);
#pragma unroll
            for (int ngl = 0; ngl < 2; ngl++) {
                const int ng = wg * 2 + ngl;
                unsigned bh[4];
                uint32_t sw = sw128((ng * 16 + brow) * 128 + kc * 32 + bkb);
                LDSM4(bh[0], bh[1], bh[2], bh[3], kbase + sw);
                mma_f16(sacc[2 * ngl], qh, &bh[0]);
                mma_f16(sacc[2 * ngl + 1], qh, &bh[2]);
                mma_f16(sacc[2 * ngl], ql, &bh[0]);
                mma_f16(sacc[2 * ngl + 1], ql, &bh[2]);
            }
        }

        // ---- softmax epilogue (fp16 wm) ----
        unsigned pH[2][4], pL[2][4];
        const char* wmp = sm + OFF_WM(s) + er * WMB + (wg * 32 + tcol) * 2;
#pragma unroll
        for (int nt = 0; nt < 4; nt++) {
            float2 w0 = __half22float2(*(const __half2*)(wmp + nt * 16));
            float2 w1 = __half22float2(*(const __half2*)(wmp + 8 * WMB + nt * 16));
            float t00 = fminf(fmaxf(sacc[nt][0] + w0.x, -10.f), 10.f);
            float t01 = fminf(fmaxf(sacc[nt][1] + w0.y, -10.f), 10.f);
            float t10 = fminf(fmaxf(sacc[nt][2] + w1.x, -10.f), 10.f);
            float t11 = fminf(fmaxf(sacc[nt][3] + w1.y, -10.f), 10.f);
            float p00 = __expf(t00 - 10.f), p01 = __expf(t01 - 10.f);
            float p10 = __expf(t10 - 10.f), p11 = __expf(t11 - 10.f);
            lsum0 += p00 + p01;
            lsum1 += p10 + p11;
            unsigned h0, l0, h1, l1;
            cvt_pack_h(p00, p01, h0, l0);
            cvt_pack_h(p10, p11, h1, l1);
            int kt = nt >> 1, j = (nt & 1) * 2;
            pH[kt][j] = h0; pH[kt][j + 1] = h1;
            pL[kt][j] = l0; pL[kt][j + 1] = l1;
        }

        // ---- O += P(wg half) V(wg keys) : (ph+pl)·vh ----
        const uint32_t vbase = smb + OFF_V(s);
#pragma unroll
        for (int ktl = 0; ktl < 2; ktl++) {
            const int kt = wg * 2 + ktl;
#pragma unroll
            for (int ng = 0; ng < 4; ng++) {
                unsigned bh[4];
                uint32_t sw = sw128((ng * 16 + brow) * 128 + kt * 32 + bkb);
                LDSM4(bh[0], bh[1], bh[2], bh[3], vbase + sw);
                mma_f16(oacc[2 * ng], pH[ktl], &bh[0]);
                mma_f16(oacc[2 * ng + 1], pH[ktl], &bh[2]);
                mma_f16(oacc[2 * ng], pL[ktl], &bh[0]);
                mma_f16(oacc[2 * ng + 1], pL[ktl], &bh[2]);
            }
        }

        // end-of-body prefetch into stage (bt+2)%3 — last read at tile bt-1,
        // whose readers all passed this tile's top barrier. No second barrier.
        if (bt + 2 < NT) load_tiles(smb, tid, h, a0, bt + 2);
        CP_COMMIT();
    }

    CP_WAITG(0);
    __syncthreads();   // all compute done before smem reuse below

    // ---- combine the two warpgroup halves ----
    lsum0 += __shfl_xor_sync(0xFFFFFFFFu, lsum0, 1);
    lsum0 += __shfl_xor_sync(0xFFFFFFFFu, lsum0, 2);
    lsum1 += __shfl_xor_sync(0xFFFFFFFFu, lsum1, 1);
    lsum1 += __shfl_xor_sync(0xFFFFFFFFu, lsum1, 2);

    float* sls = (float*)(sm + OFF_LS);
    float* soc = (float*)(sm + OFF_OC);
    if ((lane & 3) == 0) {
        sls[wg * 128 + er] = lsum0;
        sls[wg * 128 + er + 8] = lsum1;
    }
    if (wg == 1) {
#pragma unroll
        for (int ng = 0; ng < 4; ng++)
#pragma unroll
            for (int j = 0; j < 2; j++) {
                int c = ng * 16 + j * 8 + tcol;
                *(float2*)&soc[er * 64 + c] =
                    make_float2(oacc[2 * ng + j][0], oacc[2 * ng + j][1]);
                *(float2*)&soc[(er + 8) * 64 + c] =
                    make_float2(oacc[2 * ng + j][2], oacc[2 * ng + j][3]);
            }
    }
    __syncthreads();
    if (wg == 0) {
        const float inv0 = 0.25f / (sls[er] + sls[128 + er]);
        const float inv1 = 0.25f / (sls[er + 8] + sls[128 + er + 8]);
        float* d0 = &g_ctx[((size_t)h * NA + a0 + er) * DKK + tcol];
        float* d1 = d0 + 8 * DKK;
#pragma unroll
        for (int ng = 0; ng < 4; ng++)
#pragma unroll
            for (int j = 0; j < 2; j++) {
                int c = ng * 16 + j * 8 + tcol;
                float2 u0 = *(float2*)&soc[er * 64 + c];
                float2 u1 = *(float2*)&soc[(er + 8) * 64 + c];
                *(float2*)(d0 + ng * 16 + j * 8) =
                    make_float2((oacc[2 * ng + j][0] + u0.x) * inv0,
                                (oacc[2 * ng + j][1] + u0.y) * inv0);
                *(float2*)(d1 + ng * 16 + j * 8) =
                    make_float2((oacc[2 * ng + j][2] + u1.x) * inv1,
                                (oacc[2 * ng + j][3] + u1.y) * inv1);
            }
    }
}

// ---------------- final reduce ----------------
__global__ void __launch_bounds__(256) reduce_kernel(float* __restrict__ out) {
    int idx = blockIdx.x * 256 + threadIdx.x;
    const int NC = NA * DKK;
    if (idx < NC) {
        out[idx] = g_ctx[idx] + g_ctx[idx + NC] + g_ctx[idx + 2 * NC] + g_ctx[idx + 3 * NC];
    } else if (idx < NC + NA) {
        out[idx] = 1.0f;
    }
}

// ---------------- launch ----------------
extern "C" void kernel_launch(void* const* d_in, const int* in_sizes, int n_in,
                              void* d_out, int out_size)
{
    const float* a_z    = (const float*)d_in[0];
    const float* bv_z   = (const float*)d_in[1];
    const void*  mask   = d_in[2];
    const float* weight = (const float*)d_in[3];
    const float* Wq     = (const float*)d_in[4];
    const float* Wk     = (const float*)d_in[5];
    const float* Wv     = (const float*)d_in[6];
    float* out = (float*)d_out;

    detect_mask_kind<<<1, 1024>>>((const unsigned int*)mask);
    prep_wm<<<8192, 256>>>((const float4*)weight, mask);

    cudaFuncSetAttribute(proj_mma, cudaFuncAttributeMaxDynamicSharedMemorySize, PJ_SMEM);
    proj_mma<<<dim3(NA / 128, 2, 3), 256, PJ_SMEM>>>(a_z, bv_z, Wq, Wk, Wv);

    cudaFuncSetAttribute(attn_kernel, cudaFuncAttributeMaxDynamicSharedMemorySize, SMEM_BYTES);
    attn_kernel<<<dim3(NA / BM, HH), 512, SMEM_BYTES>>>();

    reduce_kernel<<<(NA * DKK + NA + 255) / 256, 256>>>(out);
}

// round 11
// speedup vs baseline: 1.4480x; 1.4480x over previous
#include <cuda_runtime.h>
#include <cuda_bf16.h>
#include <cuda_fp16.h>
#include <cstdint>

#define NA 4096
#define NB 4096
#define DD 256
#define HH 4
#define DKK 64
#define BM 128
#define BC 64
#define NT (NB / BC)

// ---------------- device scratch ----------------
__device__ __half g_Qhi[HH * NA * DKK];
__device__ __half g_Qlo[HH * NA * DKK];
__device__ __half g_Kh[HH * NB * DKK];
__device__ __half g_Vth[HH * DKK * NB];          // [h][dk][token]
__device__ __half g_wm[(size_t)NA * NB];         // fp16: san(weight) + (mask?0:-1e4)
__device__ float g_ctx[HH * NA * DKK];
__device__ int g_mask_kind;

// ---------------- helpers ----------------
__device__ __forceinline__ uint32_t smem_u32(const void* p) {
    uint32_t a;
    asm("{ .reg .u64 t; cvta.to.shared.u64 t, %1; cvt.u32.u64 %0, t; }" : "=r"(a) : "l"(p));
    return a;
}
__device__ __forceinline__ uint32_t sw128(uint32_t o) { return o ^ ((o >> 3) & 0x70); }

#define CP_ASYNC16(dst, src) \
    asm volatile("cp.async.cg.shared.global [%0], [%1], 16;\n" :: "r"(dst), "l"(src))
#define CP_COMMIT()  asm volatile("cp.async.commit_group;\n" ::: "memory")
#define CP_WAITG(n)  asm volatile("cp.async.wait_group %0;\n" :: "n"(n) : "memory")

#define LDSM4(r0, r1, r2, r3, a) \
    asm volatile("ldmatrix.sync.aligned.m8n8.x4.shared.b16 {%0,%1,%2,%3}, [%4];" \
                 : "=r"(r0), "=r"(r1), "=r"(r2), "=r"(r3) : "r"(a))

__device__ __forceinline__ void mma_f16(float* c, const unsigned* a, const unsigned* b) {
    asm volatile(
        "mma.sync.aligned.m16n8k16.row.col.f32.f16.f16.f32 "
        "{%0,%1,%2,%3}, {%4,%5,%6,%7}, {%8,%9}, {%0,%1,%2,%3};\n"
        : "+f"(c[0]), "+f"(c[1]), "+f"(c[2]), "+f"(c[3])
        : "r"(a[0]), "r"(a[1]), "r"(a[2]), "r"(a[3]), "r"(b[0]), "r"(b[1]));
}

__device__ __forceinline__ void cvt_pack_h(float x0, float x1, unsigned& hi, unsigned& lo) {
    __half h0 = __float2half_rn(x0), h1 = __float2half_rn(x1);
    __half l0 = __float2half_rn(x0 - __half2float(h0));
    __half l1 = __float2half_rn(x1 - __half2float(h1));
    hi = ((unsigned)__half_as_ushort(h1) << 16) | (unsigned)__half_as_ushort(h0);
    lo = ((unsigned)__half_as_ushort(l1) << 16) | (unsigned)__half_as_ushort(l0);
}
__device__ __forceinline__ unsigned pack_h(float x0, float x1) {
    return ((unsigned)__half_as_ushort(__float2half_rn(x1)) << 16)
         | (unsigned)__half_as_ushort(__float2half_rn(x0));
}

__device__ __forceinline__ float san(float x) {
    if (isnan(x)) return 0.f;
    if (isinf(x)) return x > 0.f ? 1.f : -1.f;
    return x;
}

// ---------------- mask dtype detector ----------------
__global__ void detect_mask_kind(const unsigned int* __restrict__ m) {
    __shared__ int s_i32, s_f32;
    if (threadIdx.x == 0) { s_i32 = 1; s_f32 = 1; }
    __syncthreads();
    int ok_i = 1, ok_f = 1;
    for (int i = threadIdx.x; i < 4096; i += 1024) {
        unsigned v = m[i];
        ok_i &= (v <= 1u);
        ok_f &= (v == 0u || v == 0x3F800000u);
    }
    if (!ok_i) atomicAnd(&s_i32, 0);
    if (!ok_f) atomicAnd(&s_f32, 0);
    __syncthreads();
    if (threadIdx.x == 0) g_mask_kind = s_i32 ? 1 : (s_f32 ? 2 : 0);
}

// ---------------- prep: fold sanitize + mask into fp16 weight ----------------
__global__ void __launch_bounds__(256) prep_wm(const float4* __restrict__ w4,
                                               const void* __restrict__ mraw) {
    const int kind = g_mask_kind;
    const size_t n4 = (size_t)NA * NB / 4;
    size_t i = (size_t)blockIdx.x * 256 + threadIdx.x;
    const size_t stride = (size_t)gridDim.x * 256;
    for (; i < n4; i += stride) {
        float4 w = w4[i];
        w.x = san(w.x); w.y = san(w.y); w.z = san(w.z); w.w = san(w.w);
        int b0, b1, b2, b3;
        if (kind == 1) {
            int4 m = ((const int4*)mraw)[i];
            b0 = m.x != 0; b1 = m.y != 0; b2 = m.z != 0; b3 = m.w != 0;
        } else if (kind == 2) {
            float4 m = ((const float4*)mraw)[i];
            b0 = m.x != 0.f; b1 = m.y != 0.f; b2 = m.z != 0.f; b3 = m.w != 0.f;
        } else {
            uchar4 m = ((const uchar4*)mraw)[i];
            b0 = m.x != 0; b1 = m.y != 0; b2 = m.z != 0; b3 = m.w != 0;
        }
        float ox = w.x + (b0 ? 0.f : -10000.f);
        float oy = w.y + (b1 ? 0.f : -10000.f);
        float oz = w.z + (b2 ? 0.f : -10000.f);
        float ow = w.w + (b3 ? 0.f : -10000.f);
        uint2 pk = make_uint2(pack_h(ox, oy), pack_h(oz, ow));
        *(uint2*)&g_wm[i * 4] = pk;
    }
}

// ---------------- projections: fp16 2-term (X hi/lo, W single) ----------------
#define PJ_XF(s)  ((s) * 32768)
#define PJ_WF(s)  (65536 + (s) * 32768)
#define PJ_XHI 131072
#define PJ_XLO 147456
#define PJ_WH  163840
#define PJ_SMEM 180224
#define VT_PITCH 132

__global__ void __launch_bounds__(256, 1) proj_mma(
    const float* __restrict__ a_z, const float* __restrict__ bv_z,
    const float* __restrict__ Wq, const float* __restrict__ Wk, const float* __restrict__ Wv)
{
    extern __shared__ char sm[];
    const uint32_t smb = smem_u32(sm);
    const int tid = threadIdx.x, wid = tid >> 5, lane = tid & 31;
    const int mat = blockIdx.z;
    const int m0 = blockIdx.x * 128, nb = blockIdx.y * 128;
    const float* X = (mat == 0) ? a_z : bv_z;
    const float* W = (mat == 0) ? Wq : (mat == 1 ? Wk : Wv);

    auto load_chunk = [&](int c) {
        const int s = c & 1;
        for (int i = tid; i < 2048; i += 256) {
            int r = i >> 4, q = i & 15;
            CP_ASYNC16(smb + PJ_XF(s) + r * 256 + q * 16,
                       (const char*)&X[(size_t)(m0 + r) * DD + c * 64] + q * 16);
            CP_ASYNC16(smb + PJ_WF(s) + r * 256 + q * 16,
                       (const char*)&W[(size_t)(nb + r) * DD + c * 64] + q * 16);
        }
    };
    load_chunk(0); CP_COMMIT();
    load_chunk(1); CP_COMMIT();

    float oacc[16][4];
#pragma unroll
    for (int nt = 0; nt < 16; nt++)
#pragma unroll
        for (int e = 0; e < 4; e++) oacc[nt][e] = 0.f;

    const int arow = wid * 16 + (lane & 15);
    const int akb = (lane >> 4) * 16;
    const int brow = (lane & 7) + ((lane >> 4) << 3);
    const int bkb = ((lane >> 3) & 1) * 16;

    for (int c = 0; c < 4; c++) {
        const int s = c & 1;
        CP_WAITG(1);
        __syncthreads();
#pragma unroll
        for (int j = 0; j < 16; j++) {
            int p = tid + j * 256;
            int r = p >> 5, cp2 = p & 31;
            float2 xv = *(const float2*)(sm + PJ_XF(s) + r * 256 + cp2 * 8);
            float2 wv = *(const float2*)(sm + PJ_WF(s) + r * 256 + cp2 * 8);
            unsigned hi, lo;
            cvt_pack_h(san(xv.x), san(xv.y), hi, lo);
            uint32_t off = sw128(r * 128 + cp2 * 4);
            *(uint32_t*)(sm + PJ_XHI + off) = hi;
            *(uint32_t*)(sm + PJ_XLO + off) = lo;
            *(uint32_t*)(sm + PJ_WH + off) = pack_h(wv.x, wv.y);
        }
        __syncthreads();
#pragma unroll
        for (int kc = 0; kc < 4; kc++) {
            unsigned ah[4], al[4];
            uint32_t asw = sw128(arow * 128 + kc * 32 + akb);
            LDSM4(ah[0], ah[1], ah[2], ah[3], smb + PJ_XHI + asw);
            LDSM4(al[0], al[1], al[2], al[3], smb + PJ_XLO + asw);
#pragma unroll
            for (int ng = 0; ng < 8; ng++) {
                unsigned bh[4];
                uint32_t bsw = sw128((ng * 16 + brow) * 128 + kc * 32 + bkb);
                LDSM4(bh[0], bh[1], bh[2], bh[3], smb + PJ_WH + bsw);
                mma_f16(oacc[2 * ng], ah, &bh[0]);
                mma_f16(oacc[2 * ng + 1], ah, &bh[2]);
                mma_f16(oacc[2 * ng], al, &bh[0]);
                mma_f16(oacc[2 * ng + 1], al, &bh[2]);
            }
        }
        __syncthreads();
        if (c + 2 < 4) load_chunk(c + 2);
        CP_COMMIT();
    }

    const int er = wid * 16 + (lane >> 2);
    const int tcol = (lane & 3) * 2;

    if (mat == 2) {
        float* smf = (float*)sm;
#pragma unroll
        for (int nt = 0; nt < 16; nt++)
#pragma unroll
            for (int hf = 0; hf < 2; hf++) {
                int row = er + hf * 8;
                int col = nt * 8 + tcol;
                smf[(col) * VT_PITCH + row] = oacc[nt][2 * hf];
                smf[(col + 1) * VT_PITCH + row] = oacc[nt][2 * hf + 1];
            }
        __syncthreads();
        for (int idx = tid; idx < 128 * 32; idx += 256) {
            int c = idx >> 5, tb = idx & 31;
            const float* src = &smf[c * VT_PITCH + tb * 4];
            unsigned u0 = pack_h(src[0], src[1]);
            unsigned u1 = pack_h(src[2], src[3]);
            int col = nb + c;
            int head = col >> 6, cc = col & 63;
            size_t o = (size_t)(head * DKK + cc) * NB + m0 + tb * 4;
            *(uint2*)&g_Vth[o] = make_uint2(u0, u1);
        }
    } else if (mat == 0) {
#pragma unroll
        for (int nt = 0; nt < 16; nt++)
#pragma unroll
            for (int hf = 0; hf < 2; hf++) {
                int row = m0 + er + hf * 8;
                int col = nb + nt * 8 + tcol;
                int head = col >> 6, cc = col & 63;
                float x0 = oacc[nt][2 * hf] * 0.125f;
                float x1 = oacc[nt][2 * hf + 1] * 0.125f;
                unsigned hi, lo;
                cvt_pack_h(x0, x1, hi, lo);
                size_t o = (size_t)(head * NA + row) * DKK + cc;
                *(unsigned*)&g_Qhi[o] = hi;
                *(unsigned*)&g_Qlo[o] = lo;
            }
    } else {
#pragma unroll
        for (int nt = 0; nt < 16; nt++)
#pragma unroll
            for (int hf = 0; hf < 2; hf++) {
                int row = m0 + er + hf * 8;
                int col = nb + nt * 8 + tcol;
                int head = col >> 6, cc = col & 63;
                unsigned u = pack_h(oacc[nt][2 * hf], oacc[nt][2 * hf + 1]);
                size_t o = (size_t)(head * NA + row) * DKK + cc;
                *(unsigned*)&g_Kh[o] = u;
            }
    }
}

// ---------------- attention smem layout: 2-stage (R9 structure), fp16 wm ----------------
#define WMB 144                              // wm row pitch bytes (128 data + 16 pad)
#define OFF_Q 0                              // QHI 16384 + QLO 16384
#define OFF_KS(s)  (32768 + (s) * 8192)
#define OFF_VS(s)  (49152 + (s) * 8192)
#define OFF_WMS(s) (65536 + (s) * 18432)     // ends at 102400
#define OFF_OC 32768      // O-combine (reuses K/V stages after mainloop)
#define OFF_LS 0          // lsum combine (reuses Q region)
#define SMEM_BYTES 102400

__device__ __forceinline__ void load_tiles(uint32_t smb, int tid, int h, int a0, int bt) {
    const int s = bt & 1, b0 = bt * BC;
    {
        int r = tid >> 3, c = tid & 7;              // 512 threads = 64 rows x 8 chunks
        uint32_t sw = sw128(r * 128 + c * 16);
        CP_ASYNC16(smb + OFF_KS(s) + sw,
                   (const char*)&g_Kh[((size_t)h * NB + b0 + r) * DKK] + c * 16);
        CP_ASYNC16(smb + OFF_VS(s) + sw,
                   (const char*)&g_Vth[((size_t)(h * DKK + r)) * NB + b0] + c * 16);
    }
    for (int i = tid; i < 1024; i += 512) {         // wm fp16: 128 rows x 128B
        int r = i >> 3, c = i & 7;
        CP_ASYNC16(smb + OFF_WMS(s) + r * WMB + c * 16,
                   (const char*)&g_wm[(size_t)(a0 + r) * NB + b0] + c * 16);
    }
}

// ---------------- attention mainloop: 512 threads, R9 schedule, fp16 wm ----------------
__global__ void __launch_bounds__(512, 1) attn_kernel() {
    extern __shared__ char sm[];
    const uint32_t smb = smem_u32(sm);
    const int tid = threadIdx.x, wid = tid >> 5, lane = tid & 31;
    const int wg = wid >> 3, wrow = wid & 7;
    const int a0 = blockIdx.x * BM, h = blockIdx.y;

    for (int i = tid; i < 1024; i += 512) {
        int r = i >> 3, c = i & 7;
        uint32_t sw = sw128(r * 128 + c * 16);
        CP_ASYNC16(smb + OFF_Q + sw,
                   (const char*)&g_Qhi[((size_t)h * NA + a0 + r) * DKK] + c * 16);
        CP_ASYNC16(smb + OFF_Q + 16384 + sw,
                   (const char*)&g_Qlo[((size_t)h * NA + a0 + r) * DKK] + c * 16);
    }
    CP_COMMIT();
    load_tiles(smb, tid, h, a0, 0); CP_COMMIT();
    load_tiles(smb, tid, h, a0, 1); CP_COMMIT();

    float oacc[8][4];
#pragma unroll
    for (int nt = 0; nt < 8; nt++)
#pragma unroll
        for (int e = 0; e < 4; e++) oacc[nt][e] = 0.f;
    float lsum0 = 0.f, lsum1 = 0.f;

    const int qrow = wrow * 16 + (lane & 15);
    const int qcb = (lane >> 4) * 16;
    const int brow = (lane & 7) + ((lane >> 4) << 3);
    const int bkb = ((lane >> 3) & 1) * 16;
    const int er = wrow * 16 + (lane >> 2);
    const int tcol = (lane & 3) * 2;

    CP_WAITG(2);
    __syncthreads();

    for (int bt = 0; bt < NT; bt++) {
        const int s = bt & 1;
        CP_WAITG(1);
        __syncthreads();

        // ---- S(wg half) = Q K^T : (qh+ql)·kh ----
        float sacc[4][4];
#pragma unroll
        for (int nt = 0; nt < 4; nt++)
#pragma unroll
            for (int e = 0; e < 4; e++) sacc[nt][e] = 0.f;

        const uint32_t kbase = smb + OFF_KS(s);
#pragma unroll
        for (int kc = 0; kc < 4; kc++) {
            unsigned qh[4], ql[4];
            uint32_t qsw = sw128(qrow * 128 + kc * 32 + qcb);
            LDSM4(qh[0], qh[1], qh[2], qh[3], smb + OFF_Q + qsw);
            LDSM4(ql[0], ql[1], ql[2], ql[3], smb + OFF_Q + 16384 + qsw);
#pragma unroll
            for (int ngl = 0; ngl < 2; ngl++) {
                const int ng = wg * 2 + ngl;
                unsigned bh[4];
                uint32_t sw = sw128((ng * 16 + brow) * 128 + kc * 32 + bkb);
                LDSM4(bh[0], bh[1], bh[2], bh[3], kbase + sw);
                mma_f16(sacc[2 * ngl], qh, &bh[0]);
                mma_f16(sacc[2 * ngl + 1], qh, &bh[2]);
                mma_f16(sacc[2 * ngl], ql, &bh[0]);
                mma_f16(sacc[2 * ngl + 1], ql, &bh[2]);
            }
        }

        // ---- softmax epilogue (fp16 wm), P split to fp16 hi/lo ----
        unsigned pH[2][4], pL[2][4];
        const char* wmp = sm + OFF_WMS(s) + er * WMB + (wg * 32 + tcol) * 2;
#pragma unroll
        for (int nt = 0; nt < 4; nt++) {
            float2 w0 = __half22float2(*(const __half2*)(wmp + nt * 16));
            float2 w1 = __half22float2(*(const __half2*)(wmp + 8 * WMB + nt * 16));
            float t00 = fminf(fmaxf(sacc[nt][0] + w0.x, -10.f), 10.f);
            float t01 = fminf(fmaxf(sacc[nt][1] + w0.y, -10.f), 10.f);
            float t10 = fminf(fmaxf(sacc[nt][2] + w1.x, -10.f), 10.f);
            float t11 = fminf(fmaxf(sacc[nt][3] + w1.y, -10.f), 10.f);
            float p00 = __expf(t00 - 10.f), p01 = __expf(t01 - 10.f);
            float p10 = __expf(t10 - 10.f), p11 = __expf(t11 - 10.f);
            lsum0 += p00 + p01;
            lsum1 += p10 + p11;
            unsigned h0, l0, h1, l1;
            cvt_pack_h(p00, p01, h0, l0);
            cvt_pack_h(p10, p11, h1, l1);
            int kt = nt >> 1, j = (nt & 1) * 2;
            pH[kt][j] = h0; pH[kt][j + 1] = h1;
            pL[kt][j] = l0; pL[kt][j + 1] = l1;
        }

        // ---- O += P(wg half) V(wg keys) : (ph+pl)·vh ----
        const uint32_t vbase = smb + OFF_VS(s);
#pragma unroll
        for (int ktl = 0; ktl < 2; ktl++) {
            const int kt = wg * 2 + ktl;
#pragma unroll
            for (int ng = 0; ng < 4; ng++) {
                unsigned bh[4];
                uint32_t sw = sw128((ng * 16 + brow) * 128 + kt * 32 + bkb);
                LDSM4(bh[0], bh[1], bh[2], bh[3], vbase + sw);
                mma_f16(oacc[2 * ng], pH[ktl], &bh[0]);
                mma_f16(oacc[2 * ng + 1], pH[ktl], &bh[2]);
                mma_f16(oacc[2 * ng], pL[ktl], &bh[0]);
                mma_f16(oacc[2 * ng + 1], pL[ktl], &bh[2]);
            }
        }

        __syncthreads();
        if (bt + 2 < NT) load_tiles(smb, tid, h, a0, bt + 2);
        CP_COMMIT();
    }

    // ---- combine the two warpgroup halves ----
    lsum0 += __shfl_xor_sync(0xFFFFFFFFu, lsum0, 1);
    lsum0 += __shfl_xor_sync(0xFFFFFFFFu, lsum0, 2);
    lsum1 += __shfl_xor_sync(0xFFFFFFFFu, lsum1, 1);
    lsum1 += __shfl_xor_sync(0xFFFFFFFFu, lsum1, 2);

    float* sls = (float*)(sm + OFF_LS);
    float* soc = (float*)(sm + OFF_OC);
    if ((lane & 3) == 0) {
        sls[wg * 128 + er] = lsum0;
        sls[wg * 128 + er + 8] = lsum1;
    }
    if (wg == 1) {
#pragma unroll
        for (int ng = 0; ng < 4; ng++)
#pragma unroll
            for (int j = 0; j < 2; j++) {
                int c = ng * 16 + j * 8 + tcol;
                *(float2*)&soc[er * 64 + c] =
                    make_float2(oacc[2 * ng + j][0], oacc[2 * ng + j][1]);
                *(float2*)&soc[(er + 8) * 64 + c] =
                    make_float2(oacc[2 * ng + j][2], oacc[2 * ng + j][3]);
            }
    }
    __syncthreads();
    if (wg == 0) {
        const float inv0 = 0.25f / (sls[er] + sls[128 + er]);
        const float inv1 = 0.25f / (sls[er + 8] + sls[128 + er + 8]);
        float* d0 = &g_ctx[((size_t)h * NA + a0 + er) * DKK + tcol];
        float* d1 = d0 + 8 * DKK;
#pragma unroll
        for (int ng = 0; ng < 4; ng++)
#pragma unroll
            for (int j = 0; j < 2; j++) {
                int c = ng * 16 + j * 8 + tcol;
                float2 u0 = *(float2*)&soc[er * 64 + c];
                float2 u1 = *(float2*)&soc[(er + 8) * 64 + c];
                *(float2*)(d0 + ng * 16 + j * 8) =
                    make_float2((oacc[2 * ng + j][0] + u0.x) * inv0,
                                (oacc[2 * ng + j][1] + u0.y) * inv0);
                *(float2*)(d1 + ng * 16 + j * 8) =
                    make_float2((oacc[2 * ng + j][2] + u1.x) * inv1,
                                (oacc[2 * ng + j][3] + u1.y) * inv1);
            }
    }
}

// ---------------- final reduce ----------------
__global__ void __launch_bounds__(256) reduce_kernel(float* __restrict__ out) {
    int idx = blockIdx.x * 256 + threadIdx.x;
    const int NC = NA * DKK;
    if (idx < NC) {
        out[idx] = g_ctx[idx] + g_ctx[idx + NC] + g_ctx[idx + 2 * NC] + g_ctx[idx + 3 * NC];
    } else if (idx < NC + NA) {
        out[idx] = 1.0f;
    }
}

// ---------------- launch ----------------
extern "C" void kernel_launch(void* const* d_in, const int* in_sizes, int n_in,
                              void* d_out, int out_size)
{
    const float* a_z    = (const float*)d_in[0];
    const float* bv_z   = (const float*)d_in[1];
    const void*  mask   = d_in[2];
    const float* weight = (const float*)d_in[3];
    const float* Wq     = (const float*)d_in[4];
    const float* Wk     = (const float*)d_in[5];
    const float* Wv     = (const float*)d_in[6];
    float* out = (float*)d_out;

    detect_mask_kind<<<1, 1024>>>((const unsigned int*)mask);
    prep_wm<<<8192, 256>>>((const float4*)weight, mask);

    cudaFuncSetAttribute(proj_mma, cudaFuncAttributeMaxDynamicSharedMemorySize, PJ_SMEM);
    proj_mma<<<dim3(NA / 128, 2, 3), 256, PJ_SMEM>>>(a_z, bv_z, Wq, Wk, Wv);

    cudaFuncSetAttribute(attn_kernel, cudaFuncAttributeMaxDynamicSharedMemorySize, SMEM_BYTES);
    attn_kernel<<<dim3(NA / BM, HH), 512, SMEM_BYTES>>>();

    reduce_kernel<<<(NA * DKK + NA + 255) / 256, 256>>>(out);
}

// round 12
// speedup vs baseline: 1.4943x; 1.0320x over previous
#include <cuda_runtime.h>
#include <cuda_bf16.h>
#include <cuda_fp16.h>
#include <cstdint>

#define NA 4096
#define NB 4096
#define DD 256
#define HH 4
#define DKK 64
#define BMA 64          // attn rows per CTA (2 CTAs/SM)
#define BC 64
#define NT (NB / BC)

// ---------------- device scratch ----------------
__device__ __half g_Qhi[HH * NA * DKK];
__device__ __half g_Qlo[HH * NA * DKK];
__device__ __half g_Kh[HH * NB * DKK];
__device__ __half g_Vth[HH * DKK * NB];          // [h][dk][token]
__device__ __half g_wm[(size_t)NA * NB];         // fp16: san(weight) + (mask?0:-1e4)
__device__ float g_ctx[HH * NA * DKK];
__device__ int g_mask_kind;

// ---------------- helpers ----------------
__device__ __forceinline__ uint32_t smem_u32(const void* p) {
    uint32_t a;
    asm("{ .reg .u64 t; cvta.to.shared.u64 t, %1; cvt.u32.u64 %0, t; }" : "=r"(a) : "l"(p));
    return a;
}
__device__ __forceinline__ uint32_t sw128(uint32_t o) { return o ^ ((o >> 3) & 0x70); }

#define CP_ASYNC16(dst, src) \
    asm volatile("cp.async.cg.shared.global [%0], [%1], 16;\n" :: "r"(dst), "l"(src))
#define CP_COMMIT()  asm volatile("cp.async.commit_group;\n" ::: "memory")
#define CP_WAITG(n)  asm volatile("cp.async.wait_group %0;\n" :: "n"(n) : "memory")

#define LDSM4(r0, r1, r2, r3, a) \
    asm volatile("ldmatrix.sync.aligned.m8n8.x4.shared.b16 {%0,%1,%2,%3}, [%4];" \
                 : "=r"(r0), "=r"(r1), "=r"(r2), "=r"(r3) : "r"(a))

__device__ __forceinline__ void mma_f16(float* c, const unsigned* a, const unsigned* b) {
    asm volatile(
        "mma.sync.aligned.m16n8k16.row.col.f32.f16.f16.f32 "
        "{%0,%1,%2,%3}, {%4,%5,%6,%7}, {%8,%9}, {%0,%1,%2,%3};\n"
        : "+f"(c[0]), "+f"(c[1]), "+f"(c[2]), "+f"(c[3])
        : "r"(a[0]), "r"(a[1]), "r"(a[2]), "r"(a[3]), "r"(b[0]), "r"(b[1]));
}

__device__ __forceinline__ void cvt_pack_h(float x0, float x1, unsigned& hi, unsigned& lo) {
    __half h0 = __float2half_rn(x0), h1 = __float2half_rn(x1);
    __half l0 = __float2half_rn(x0 - __half2float(h0));
    __half l1 = __float2half_rn(x1 - __half2float(h1));
    hi = ((unsigned)__half_as_ushort(h1) << 16) | (unsigned)__half_as_ushort(h0);
    lo = ((unsigned)__half_as_ushort(l1) << 16) | (unsigned)__half_as_ushort(l0);
}
__device__ __forceinline__ unsigned pack_h(float x0, float x1) {
    return ((unsigned)__half_as_ushort(__float2half_rn(x1)) << 16)
         | (unsigned)__half_as_ushort(__float2half_rn(x0));
}

__device__ __forceinline__ float san(float x) {
    if (isnan(x)) return 0.f;
    if (isinf(x)) return x > 0.f ? 1.f : -1.f;
    return x;
}

// ---------------- mask dtype detector ----------------
__global__ void detect_mask_kind(const unsigned int* __restrict__ m) {
    __shared__ int s_i32, s_f32;
    if (threadIdx.x == 0) { s_i32 = 1; s_f32 = 1; }
    __syncthreads();
    int ok_i = 1, ok_f = 1;
    for (int i = threadIdx.x; i < 4096; i += 1024) {
        unsigned v = m[i];
        ok_i &= (v <= 1u);
        ok_f &= (v == 0u || v == 0x3F800000u);
    }
    if (!ok_i) atomicAnd(&s_i32, 0);
    if (!ok_f) atomicAnd(&s_f32, 0);
    __syncthreads();
    if (threadIdx.x == 0) g_mask_kind = s_i32 ? 1 : (s_f32 ? 2 : 0);
}

// ---------------- prep: fold sanitize + mask into fp16 weight ----------------
__global__ void __launch_bounds__(256) prep_wm(const float4* __restrict__ w4,
                                               const void* __restrict__ mraw) {
    const int kind = g_mask_kind;
    const size_t n4 = (size_t)NA * NB / 4;
    size_t i = (size_t)blockIdx.x * 256 + threadIdx.x;
    const size_t stride = (size_t)gridDim.x * 256;
    for (; i < n4; i += stride) {
        float4 w = w4[i];
        w.x = san(w.x); w.y = san(w.y); w.z = san(w.z); w.w = san(w.w);
        int b0, b1, b2, b3;
        if (kind == 1) {
            int4 m = ((const int4*)mraw)[i];
            b0 = m.x != 0; b1 = m.y != 0; b2 = m.z != 0; b3 = m.w != 0;
        } else if (kind == 2) {
            float4 m = ((const float4*)mraw)[i];
            b0 = m.x != 0.f; b1 = m.y != 0.f; b2 = m.z != 0.f; b3 = m.w != 0.f;
        } else {
            uchar4 m = ((const uchar4*)mraw)[i];
            b0 = m.x != 0; b1 = m.y != 0; b2 = m.z != 0; b3 = m.w != 0;
        }
        float ox = w.x + (b0 ? 0.f : -10000.f);
        float oy = w.y + (b1 ? 0.f : -10000.f);
        float oz = w.z + (b2 ? 0.f : -10000.f);
        float ow = w.w + (b3 ? 0.f : -10000.f);
        uint2 pk = make_uint2(pack_h(ox, oy), pack_h(oz, ow));
        *(uint2*)&g_wm[i * 4] = pk;
    }
}

// ---------------- projections: fp16 2-term (X hi/lo, W single) ----------------
#define PJ_XF(s)  ((s) * 32768)
#define PJ_WF(s)  (65536 + (s) * 32768)
#define PJ_XHI 131072
#define PJ_XLO 147456
#define PJ_WH  163840
#define PJ_SMEM 180224
#define VT_PITCH 132

__global__ void __launch_bounds__(256, 1) proj_mma(
    const float* __restrict__ a_z, const float* __restrict__ bv_z,
    const float* __restrict__ Wq, const float* __restrict__ Wk, const float* __restrict__ Wv)
{
    extern __shared__ char sm[];
    const uint32_t smb = smem_u32(sm);
    const int tid = threadIdx.x, wid = tid >> 5, lane = tid & 31;
    const int mat = blockIdx.z;
    const int m0 = blockIdx.x * 128, nb = blockIdx.y * 128;
    const float* X = (mat == 0) ? a_z : bv_z;
    const float* W = (mat == 0) ? Wq : (mat == 1 ? Wk : Wv);

    auto load_chunk = [&](int c) {
        const int s = c & 1;
        for (int i = tid; i < 2048; i += 256) {
            int r = i >> 4, q = i & 15;
            CP_ASYNC16(smb + PJ_XF(s) + r * 256 + q * 16,
                       (const char*)&X[(size_t)(m0 + r) * DD + c * 64] + q * 16);
            CP_ASYNC16(smb + PJ_WF(s) + r * 256 + q * 16,
                       (const char*)&W[(size_t)(nb + r) * DD + c * 64] + q * 16);
        }
    };
    load_chunk(0); CP_COMMIT();
    load_chunk(1); CP_COMMIT();

    float oacc[16][4];
#pragma unroll
    for (int nt = 0; nt < 16; nt++)
#pragma unroll
        for (int e = 0; e < 4; e++) oacc[nt][e] = 0.f;

    const int arow = wid * 16 + (lane & 15);
    const int akb = (lane >> 4) * 16;
    const int brow = (lane & 7) + ((lane >> 4) << 3);
    const int bkb = ((lane >> 3) & 1) * 16;

    for (int c = 0; c < 4; c++) {
        const int s = c & 1;
        CP_WAITG(1);
        __syncthreads();
#pragma unroll
        for (int j = 0; j < 16; j++) {
            int p = tid + j * 256;
            int r = p >> 5, cp2 = p & 31;
            float2 xv = *(const float2*)(sm + PJ_XF(s) + r * 256 + cp2 * 8);
            float2 wv = *(const float2*)(sm + PJ_WF(s) + r * 256 + cp2 * 8);
            unsigned hi, lo;
            cvt_pack_h(san(xv.x), san(xv.y), hi, lo);
            uint32_t off = sw128(r * 128 + cp2 * 4);
            *(uint32_t*)(sm + PJ_XHI + off) = hi;
            *(uint32_t*)(sm + PJ_XLO + off) = lo;
            *(uint32_t*)(sm + PJ_WH + off) = pack_h(wv.x, wv.y);
        }
        __syncthreads();
#pragma unroll
        for (int kc = 0; kc < 4; kc++) {
            unsigned ah[4], al[4];
            uint32_t asw = sw128(arow * 128 + kc * 32 + akb);
            LDSM4(ah[0], ah[1], ah[2], ah[3], smb + PJ_XHI + asw);
            LDSM4(al[0], al[1], al[2], al[3], smb + PJ_XLO + asw);
#pragma unroll
            for (int ng = 0; ng < 8; ng++) {
                unsigned bh[4];
                uint32_t bsw = sw128((ng * 16 + brow) * 128 + kc * 32 + bkb);
                LDSM4(bh[0], bh[1], bh[2], bh[3], smb + PJ_WH + bsw);
                mma_f16(oacc[2 * ng], ah, &bh[0]);
                mma_f16(oacc[2 * ng + 1], ah, &bh[2]);
                mma_f16(oacc[2 * ng], al, &bh[0]);
                mma_f16(oacc[2 * ng + 1], al, &bh[2]);
            }
        }
        __syncthreads();
        if (c + 2 < 4) load_chunk(c + 2);
        CP_COMMIT();
    }

    const int er = wid * 16 + (lane >> 2);
    const int tcol = (lane & 3) * 2;

    if (mat == 2) {
        float* smf = (float*)sm;
#pragma unroll
        for (int nt = 0; nt < 16; nt++)
#pragma unroll
            for (int hf = 0; hf < 2; hf++) {
                int row = er + hf * 8;
                int col = nt * 8 + tcol;
                smf[(col) * VT_PITCH + row] = oacc[nt][2 * hf];
                smf[(col + 1) * VT_PITCH + row] = oacc[nt][2 * hf + 1];
            }
        __syncthreads();
        for (int idx = tid; idx < 128 * 32; idx += 256) {
            int c = idx >> 5, tb = idx & 31;
            const float* src = &smf[c * VT_PITCH + tb * 4];
            unsigned u0 = pack_h(src[0], src[1]);
            unsigned u1 = pack_h(src[2], src[3]);
            int col = nb + c;
            int head = col >> 6, cc = col & 63;
            size_t o = (size_t)(head * DKK + cc) * NB + m0 + tb * 4;
            *(uint2*)&g_Vth[o] = make_uint2(u0, u1);
        }
    } else if (mat == 0) {
#pragma unroll
        for (int nt = 0; nt < 16; nt++)
#pragma unroll
            for (int hf = 0; hf < 2; hf++) {
                int row = m0 + er + hf * 8;
                int col = nb + nt * 8 + tcol;
                int head = col >> 6, cc = col & 63;
                float x0 = oacc[nt][2 * hf] * 0.125f;
                float x1 = oacc[nt][2 * hf + 1] * 0.125f;
                unsigned hi, lo;
                cvt_pack_h(x0, x1, hi, lo);
                size_t o = (size_t)(head * NA + row) * DKK + cc;
                *(unsigned*)&g_Qhi[o] = hi;
                *(unsigned*)&g_Qlo[o] = lo;
            }
    } else {
#pragma unroll
        for (int nt = 0; nt < 16; nt++)
#pragma unroll
            for (int hf = 0; hf < 2; hf++) {
                int row = m0 + er + hf * 8;
                int col = nb + nt * 8 + tcol;
                int head = col >> 6, cc = col & 63;
                unsigned u = pack_h(oacc[nt][2 * hf], oacc[nt][2 * hf + 1]);
                size_t o = (size_t)(head * NA + row) * DKK + cc;
                *(unsigned*)&g_Kh[o] = u;
            }
    }
}

// ---------------- attention smem layout: BM=64, 2-stage, fp16 wm ----------------
#define WMB 144                              // wm row pitch bytes (128 data + 16 pad)
#define OFF_Q 0                              // QHI 8192 + QLO 8192
#define OFF_KS(s)  (16384 + (s) * 8192)      // ends 32768
#define OFF_VS(s)  (32768 + (s) * 8192)      // ends 49152
#define OFF_WMS(s) (49152 + (s) * 9216)      // ends 67584
#define OFF_OC 16384      // O-combine 64x64 f32 = 16KB (reuses K stages)
#define OFF_LS 0          // lsum combine 2x64 f32 (reuses Q region)
#define SMEM_BYTES 67584

__device__ __forceinline__ void load_tiles(uint32_t smb, int tid, int h, int a0, int bt) {
    const int s = bt & 1, b0 = bt * BC;
    for (int i = tid; i < 512; i += 256) {          // K + V: 64 rows x 8 chunks
        int r = i >> 3, c = i & 7;
        uint32_t sw = sw128(r * 128 + c * 16);
        CP_ASYNC16(smb + OFF_KS(s) + sw,
                   (const char*)&g_Kh[((size_t)h * NB + b0 + r) * DKK] + c * 16);
        CP_ASYNC16(smb + OFF_VS(s) + sw,
                   (const char*)&g_Vth[((size_t)(h * DKK + r)) * NB + b0] + c * 16);
    }
    for (int i = tid; i < 512; i += 256) {          // wm fp16: 64 rows x 128B
        int r = i >> 3, c = i & 7;
        CP_ASYNC16(smb + OFF_WMS(s) + r * WMB + c * 16,
                   (const char*)&g_wm[(size_t)(a0 + r) * NB + b0] + c * 16);
    }
}

// ---------------- attention mainloop: 256 threads, 2 CTAs/SM, R9 schedule ----------------
__global__ void __launch_bounds__(256, 2) attn_kernel() {
    extern __shared__ char sm[];
    const uint32_t smb = smem_u32(sm);
    const int tid = threadIdx.x, wid = tid >> 5, lane = tid & 31;
    const int wg = wid >> 2, wrow = wid & 3;
    const int a0 = blockIdx.x * BMA, h = blockIdx.y;

    for (int i = tid; i < 512; i += 256) {          // Q: 64 rows x 8 chunks, hi+lo
        int r = i >> 3, c = i & 7;
        uint32_t sw = sw128(r * 128 + c * 16);
        CP_ASYNC16(smb + OFF_Q + sw,
                   (const char*)&g_Qhi[((size_t)h * NA + a0 + r) * DKK] + c * 16);
        CP_ASYNC16(smb + OFF_Q + 8192 + sw,
                   (const char*)&g_Qlo[((size_t)h * NA + a0 + r) * DKK] + c * 16);
    }
    CP_COMMIT();
    load_tiles(smb, tid, h, a0, 0); CP_COMMIT();
    load_tiles(smb, tid, h, a0, 1); CP_COMMIT();

    float oacc[8][4];
#pragma unroll
    for (int nt = 0; nt < 8; nt++)
#pragma unroll
        for (int e = 0; e < 4; e++) oacc[nt][e] = 0.f;
    float lsum0 = 0.f, lsum1 = 0.f;

    const int qrow = wrow * 16 + (lane & 15);
    const int qcb = (lane >> 4) * 16;
    const int brow = (lane & 7) + ((lane >> 4) << 3);
    const int bkb = ((lane >> 3) & 1) * 16;
    const int er = wrow * 16 + (lane >> 2);
    const int tcol = (lane & 3) * 2;

    CP_WAITG(2);
    __syncthreads();

    for (int bt = 0; bt < NT; bt++) {
        const int s = bt & 1;
        CP_WAITG(1);
        __syncthreads();

        // ---- S(wg half) = Q K^T : (qh+ql)·kh ----
        float sacc[4][4];
#pragma unroll
        for (int nt = 0; nt < 4; nt++)
#pragma unroll
            for (int e = 0; e < 4; e++) sacc[nt][e] = 0.f;

        const uint32_t kbase = smb + OFF_KS(s);
#pragma unroll
        for (int kc = 0; kc < 4; kc++) {
            unsigned qh[4], ql[4];
            uint32_t qsw = sw128(qrow * 128 + kc * 32 + qcb);
            LDSM4(qh[0], qh[1], qh[2], qh[3], smb + OFF_Q + qsw);
            LDSM4(ql[0], ql[1], ql[2], ql[3], smb + OFF_Q + 8192 + qsw);
#pragma unroll
            for (int ngl = 0; ngl < 2; ngl++) {
                const int ng = wg * 2 + ngl;
                unsigned bh[4];
                uint32_t sw = sw128((ng * 16 + brow) * 128 + kc * 32 + bkb);
                LDSM4(bh[0], bh[1], bh[2], bh[3], kbase + sw);
                mma_f16(sacc[2 * ngl], qh, &bh[0]);
                mma_f16(sacc[2 * ngl + 1], qh, &bh[2]);
                mma_f16(sacc[2 * ngl], ql, &bh[0]);
                mma_f16(sacc[2 * ngl + 1], ql, &bh[2]);
            }
        }

        // ---- softmax epilogue (fp16 wm), P split to fp16 hi/lo ----
        unsigned pH[2][4], pL[2][4];
        const char* wmp = sm + OFF_WMS(s) + er * WMB + (wg * 32 + tcol) * 2;
#pragma unroll
        for (int nt = 0; nt < 4; nt++) {
            float2 w0 = __half22float2(*(const __half2*)(wmp + nt * 16));
            float2 w1 = __half22float2(*(const __half2*)(wmp + 8 * WMB + nt * 16));
            float t00 = fminf(fmaxf(sacc[nt][0] + w0.x, -10.f), 10.f);
            float t01 = fminf(fmaxf(sacc[nt][1] + w0.y, -10.f), 10.f);
            float t10 = fminf(fmaxf(sacc[nt][2] + w1.x, -10.f), 10.f);
            float t11 = fminf(fmaxf(sacc[nt][3] + w1.y, -10.f), 10.f);
            float p00 = __expf(t00 - 10.f), p01 = __expf(t01 - 10.f);
            float p10 = __expf(t10 - 10.f), p11 = __expf(t11 - 10.f);
            lsum0 += p00 + p01;
            lsum1 += p10 + p11;
            unsigned h0, l0, h1, l1;
            cvt_pack_h(p00, p01, h0, l0);
            cvt_pack_h(p10, p11, h1, l1);
            int kt = nt >> 1, j = (nt & 1) * 2;
            pH[kt][j] = h0; pH[kt][j + 1] = h1;
            pL[kt][j] = l0; pL[kt][j + 1] = l1;
        }

        // ---- O += P(wg half) V(wg keys) : (ph+pl)·vh ----
        const uint32_t vbase = smb + OFF_VS(s);
#pragma unroll
        for (int ktl = 0; ktl < 2; ktl++) {
            const int kt = wg * 2 + ktl;
#pragma unroll
            for (int ng = 0; ng < 4; ng++) {
                unsigned bh[4];
                uint32_t sw = sw128((ng * 16 + brow) * 128 + kt * 32 + bkb);
                LDSM4(bh[0], bh[1], bh[2], bh[3], vbase + sw);
                mma_f16(oacc[2 * ng], pH[ktl], &bh[0]);
                mma_f16(oacc[2 * ng + 1], pH[ktl], &bh[2]);
                mma_f16(oacc[2 * ng], pL[ktl], &bh[0]);
                mma_f16(oacc[2 * ng + 1], pL[ktl], &bh[2]);
            }
        }

        __syncthreads();
        if (bt + 2 < NT) load_tiles(smb, tid, h, a0, bt + 2);
        CP_COMMIT();
    }

    // ---- combine the two warpgroup halves ----
    lsum0 += __shfl_xor_sync(0xFFFFFFFFu, lsum0, 1);
    lsum0 += __shfl_xor_sync(0xFFFFFFFFu, lsum0, 2);
    lsum1 += __shfl_xor_sync(0xFFFFFFFFu, lsum1, 1);
    lsum1 += __shfl_xor_sync(0xFFFFFFFFu, lsum1, 2);

    float* sls = (float*)(sm + OFF_LS);
    float* soc = (float*)(sm + OFF_OC);
    if ((lane & 3) == 0) {
        sls[wg * 64 + er] = lsum0;
        sls[wg * 64 + er + 8] = lsum1;
    }
    if (wg == 1) {
#pragma unroll
        for (int ng = 0; ng < 4; ng++)
#pragma unroll
            for (int j = 0; j < 2; j++) {
                int c = ng * 16 + j * 8 + tcol;
                *(float2*)&soc[er * 64 + c] =
                    make_float2(oacc[2 * ng + j][0], oacc[2 * ng + j][1]);
                *(float2*)&soc[(er + 8) * 64 + c] =
                    make_float2(oacc[2 * ng + j][2], oacc[2 * ng + j][3]);
            }
    }
    __syncthreads();
    if (wg == 0) {
        const float inv0 = 0.25f / (sls[er] + sls[64 + er]);
        const float inv1 = 0.25f / (sls[er + 8] + sls[64 + er + 8]);
        float* d0 = &g_ctx[((size_t)h * NA + a0 + er) * DKK + tcol];
        float* d1 = d0 + 8 * DKK;
#pragma unroll
        for (int ng = 0; ng < 4; ng++)
#pragma unroll
            for (int j = 0; j < 2; j++) {
                int c = ng * 16 + j * 8 + tcol;
                float2 u0 = *(float2*)&soc[er * 64 + c];
                float2 u1 = *(float2*)&soc[(er + 8) * 64 + c];
                *(float2*)(d0 + ng * 16 + j * 8) =
                    make_float2((oacc[2 * ng + j][0] + u0.x) * inv0,
                                (oacc[2 * ng + j][1] + u0.y) * inv0);
                *(float2*)(d1 + ng * 16 + j * 8) =
                    make_float2((oacc[2 * ng + j][2] + u1.x) * inv1,
                                (oacc[2 * ng + j][3] + u1.y) * inv1);
            }
    }
}

// ---------------- final reduce ----------------
__global__ void __launch_bounds__(256) reduce_kernel(float* __restrict__ out) {
    int idx = blockIdx.x * 256 + threadIdx.x;
    const int NC = NA * DKK;
    if (idx < NC) {
        out[idx] = g_ctx[idx] + g_ctx[idx + NC] + g_ctx[idx + 2 * NC] + g_ctx[idx + 3 * NC];
    } else if (idx < NC + NA) {
        out[idx] = 1.0f;
    }
}

// ---------------- launch ----------------
extern "C" void kernel_launch(void* const* d_in, const int* in_sizes, int n_in,
                              void* d_out, int out_size)
{
    const float* a_z    = (const float*)d_in[0];
    const float* bv_z   = (const float*)d_in[1];
    const void*  mask   = d_in[2];
    const float* weight = (const float*)d_in[3];
    const float* Wq     = (const float*)d_in[4];
    const float* Wk     = (const float*)d_in[5];
    const float* Wv     = (const float*)d_in[6];
    float* out = (float*)d_out;

    detect_mask_kind<<<1, 1024>>>((const unsigned int*)mask);
    prep_wm<<<8192, 256>>>((const float4*)weight, mask);

    cudaFuncSetAttribute(proj_mma, cudaFuncAttributeMaxDynamicSharedMemorySize, PJ_SMEM);
    proj_mma<<<dim3(NA / 128, 2, 3), 256, PJ_SMEM>>>(a_z, bv_z, Wq, Wk, Wv);

    cudaFuncSetAttribute(attn_kernel, cudaFuncAttributeMaxDynamicSharedMemorySize, SMEM_BYTES);
    attn_kernel<<<dim3(NA / BMA, HH), 256, SMEM_BYTES>>>();

    reduce_kernel<<<(NA * DKK + NA + 255) / 256, 256>>>(out);
}

// round 13
// speedup vs baseline: 1.6933x; 1.1332x over previous
#include <cuda_runtime.h>
#include <cuda_bf16.h>
#include <cuda_fp16.h>
#include <cstdint>

#define NA 4096
#define NB 4096
#define DD 256
#define HH 4
#define DKK 64
#define BMA 64          // attn rows per CTA (2 CTAs/SM)
#define BC 64
#define NT (NB / BC)

// ---------------- device scratch ----------------
__device__ __half g_Qhi[HH * NA * DKK];
__device__ __half g_Qlo[HH * NA * DKK];
__device__ __half g_Kh[HH * NB * DKK];
__device__ __half g_Vth[HH * DKK * NB];          // [h][dk][token]
__device__ __half g_wm[(size_t)NA * NB];         // fp16: san(weight) + (mask?0:-1e4)
__device__ float g_ctx[HH * NA * DKK];
__device__ int g_mask_kind;

// ---------------- helpers ----------------
__device__ __forceinline__ uint32_t smem_u32(const void* p) {
    uint32_t a;
    asm("{ .reg .u64 t; cvta.to.shared.u64 t, %1; cvt.u32.u64 %0, t; }" : "=r"(a) : "l"(p));
    return a;
}
__device__ __forceinline__ uint32_t sw128(uint32_t o) { return o ^ ((o >> 3) & 0x70); }

#define CP_ASYNC16(dst, src) \
    asm volatile("cp.async.cg.shared.global [%0], [%1], 16;\n" :: "r"(dst), "l"(src))
#define CP_COMMIT()  asm volatile("cp.async.commit_group;\n" ::: "memory")
#define CP_WAITG(n)  asm volatile("cp.async.wait_group %0;\n" :: "n"(n) : "memory")

#define LDSM4(r0, r1, r2, r3, a) \
    asm volatile("ldmatrix.sync.aligned.m8n8.x4.shared.b16 {%0,%1,%2,%3}, [%4];" \
                 : "=r"(r0), "=r"(r1), "=r"(r2), "=r"(r3) : "r"(a))

__device__ __forceinline__ void mma_f16(float* c, const unsigned* a, const unsigned* b) {
    asm volatile(
        "mma.sync.aligned.m16n8k16.row.col.f32.f16.f16.f32 "
        "{%0,%1,%2,%3}, {%4,%5,%6,%7}, {%8,%9}, {%0,%1,%2,%3};\n"
        : "+f"(c[0]), "+f"(c[1]), "+f"(c[2]), "+f"(c[3])
        : "r"(a[0]), "r"(a[1]), "r"(a[2]), "r"(a[3]), "r"(b[0]), "r"(b[1]));
}

__device__ __forceinline__ void cvt_pack_h(float x0, float x1, unsigned& hi, unsigned& lo) {
    __half h0 = __float2half_rn(x0), h1 = __float2half_rn(x1);
    __half l0 = __float2half_rn(x0 - __half2float(h0));
    __half l1 = __float2half_rn(x1 - __half2float(h1));
    hi = ((unsigned)__half_as_ushort(h1) << 16) | (unsigned)__half_as_ushort(h0);
    lo = ((unsigned)__half_as_ushort(l1) << 16) | (unsigned)__half_as_ushort(l0);
}
__device__ __forceinline__ unsigned pack_h(float x0, float x1) {
    return ((unsigned)__half_as_ushort(__float2half_rn(x1)) << 16)
         | (unsigned)__half_as_ushort(__float2half_rn(x0));
}

__device__ __forceinline__ float san(float x) {
    if (isnan(x)) return 0.f;
    if (isinf(x)) return x > 0.f ? 1.f : -1.f;
    return x;
}

// ---------------- mask dtype detector ----------------
__global__ void detect_mask_kind(const unsigned int* __restrict__ m) {
    __shared__ int s_i32, s_f32;
    if (threadIdx.x == 0) { s_i32 = 1; s_f32 = 1; }
    __syncthreads();
    int ok_i = 1, ok_f = 1;
    for (int i = threadIdx.x; i < 4096; i += 1024) {
        unsigned v = m[i];
        ok_i &= (v <= 1u);
        ok_f &= (v == 0u || v == 0x3F800000u);
    }
    if (!ok_i) atomicAnd(&s_i32, 0);
    if (!ok_f) atomicAnd(&s_f32, 0);
    __syncthreads();
    if (threadIdx.x == 0) g_mask_kind = s_i32 ? 1 : (s_f32 ? 2 : 0);
}

// ---------------- prep: fold sanitize + mask into fp16 weight ----------------
__global__ void __launch_bounds__(256) prep_wm(const float4* __restrict__ w4,
                                               const void* __restrict__ mraw) {
    const int kind = g_mask_kind;
    const size_t n4 = (size_t)NA * NB / 4;
    size_t i = (size_t)blockIdx.x * 256 + threadIdx.x;
    const size_t stride = (size_t)gridDim.x * 256;
    for (; i < n4; i += stride) {
        float4 w = w4[i];
        w.x = san(w.x); w.y = san(w.y); w.z = san(w.z); w.w = san(w.w);
        int b0, b1, b2, b3;
        if (kind == 1) {
            int4 m = ((const int4*)mraw)[i];
            b0 = m.x != 0; b1 = m.y != 0; b2 = m.z != 0; b3 = m.w != 0;
        } else if (kind == 2) {
            float4 m = ((const float4*)mraw)[i];
            b0 = m.x != 0.f; b1 = m.y != 0.f; b2 = m.z != 0.f; b3 = m.w != 0.f;
        } else {
            uchar4 m = ((const uchar4*)mraw)[i];
            b0 = m.x != 0; b1 = m.y != 0; b2 = m.z != 0; b3 = m.w != 0;
        }
        float ox = w.x + (b0 ? 0.f : -10000.f);
        float oy = w.y + (b1 ? 0.f : -10000.f);
        float oz = w.z + (b2 ? 0.f : -10000.f);
        float ow = w.w + (b3 ? 0.f : -10000.f);
        uint2 pk = make_uint2(pack_h(ox, oy), pack_h(oz, ow));
        *(uint2*)&g_wm[i * 4] = pk;
    }
}

// ---------------- projections: fp16 2-term (X hi/lo, W single) ----------------
#define PJ_XF(s)  ((s) * 32768)
#define PJ_WF(s)  (65536 + (s) * 32768)
#define PJ_XHI 131072
#define PJ_XLO 147456
#define PJ_WH  163840
#define PJ_SMEM 180224
#define VT_PITCH 132

__global__ void __launch_bounds__(256, 1) proj_mma(
    const float* __restrict__ a_z, const float* __restrict__ bv_z,
    const float* __restrict__ Wq, const float* __restrict__ Wk, const float* __restrict__ Wv)
{
    extern __shared__ char sm[];
    const uint32_t smb = smem_u32(sm);
    const int tid = threadIdx.x, wid = tid >> 5, lane = tid & 31;
    const int mat = blockIdx.z;
    const int m0 = blockIdx.x * 128, nb = blockIdx.y * 128;
    const float* X = (mat == 0) ? a_z : bv_z;
    const float* W = (mat == 0) ? Wq : (mat == 1 ? Wk : Wv);

    auto load_chunk = [&](int c) {
        const int s = c & 1;
        for (int i = tid; i < 2048; i += 256) {
            int r = i >> 4, q = i & 15;
            CP_ASYNC16(smb + PJ_XF(s) + r * 256 + q * 16,
                       (const char*)&X[(size_t)(m0 + r) * DD + c * 64] + q * 16);
            CP_ASYNC16(smb + PJ_WF(s) + r * 256 + q * 16,
                       (const char*)&W[(size_t)(nb + r) * DD + c * 64] + q * 16);
        }
    };
    load_chunk(0); CP_COMMIT();
    load_chunk(1); CP_COMMIT();

    float oacc[16][4];
#pragma unroll
    for (int nt = 0; nt < 16; nt++)
#pragma unroll
        for (int e = 0; e < 4; e++) oacc[nt][e] = 0.f;

    const int arow = wid * 16 + (lane & 15);
    const int akb = (lane >> 4) * 16;
    const int brow = (lane & 7) + ((lane >> 4) << 3);
    const int bkb = ((lane >> 3) & 1) * 16;

    for (int c = 0; c < 4; c++) {
        const int s = c & 1;
        CP_WAITG(1);
        __syncthreads();
#pragma unroll
        for (int j = 0; j < 16; j++) {
            int p = tid + j * 256;
            int r = p >> 5, cp2 = p & 31;
            float2 xv = *(const float2*)(sm + PJ_XF(s) + r * 256 + cp2 * 8);
            float2 wv = *(const float2*)(sm + PJ_WF(s) + r * 256 + cp2 * 8);
            unsigned hi, lo;
            cvt_pack_h(san(xv.x), san(xv.y), hi, lo);
            uint32_t off = sw128(r * 128 + cp2 * 4);
            *(uint32_t*)(sm + PJ_XHI + off) = hi;
            *(uint32_t*)(sm + PJ_XLO + off) = lo;
            *(uint32_t*)(sm + PJ_WH + off) = pack_h(wv.x, wv.y);
        }
        __syncthreads();
#pragma unroll
        for (int kc = 0; kc < 4; kc++) {
            unsigned ah[4], al[4];
            uint32_t asw = sw128(arow * 128 + kc * 32 + akb);
            LDSM4(ah[0], ah[1], ah[2], ah[3], smb + PJ_XHI + asw);
            LDSM4(al[0], al[1], al[2], al[3], smb + PJ_XLO + asw);
#pragma unroll
            for (int ng = 0; ng < 8; ng++) {
                unsigned bh[4];
                uint32_t bsw = sw128((ng * 16 + brow) * 128 + kc * 32 + bkb);
                LDSM4(bh[0], bh[1], bh[2], bh[3], smb + PJ_WH + bsw);
                mma_f16(oacc[2 * ng], ah, &bh[0]);
                mma_f16(oacc[2 * ng + 1], ah, &bh[2]);
                mma_f16(oacc[2 * ng], al, &bh[0]);
                mma_f16(oacc[2 * ng + 1], al, &bh[2]);
            }
        }
        __syncthreads();
        if (c + 2 < 4) load_chunk(c + 2);
        CP_COMMIT();
    }

    const int er = wid * 16 + (lane >> 2);
    const int tcol = (lane & 3) * 2;

    if (mat == 2) {
        float* smf = (float*)sm;
#pragma unroll
        for (int nt = 0; nt < 16; nt++)
#pragma unroll
            for (int hf = 0; hf < 2; hf++) {
                int row = er + hf * 8;
                int col = nt * 8 + tcol;
                smf[(col) * VT_PITCH + row] = oacc[nt][2 * hf];
                smf[(col + 1) * VT_PITCH + row] = oacc[nt][2 * hf + 1];
            }
        __syncthreads();
        for (int idx = tid; idx < 128 * 32; idx += 256) {
            int c = idx >> 5, tb = idx & 31;
            const float* src = &smf[c * VT_PITCH + tb * 4];
            unsigned u0 = pack_h(src[0], src[1]);
            unsigned u1 = pack_h(src[2], src[3]);
            int col = nb + c;
            int head = col >> 6, cc = col & 63;
            size_t o = (size_t)(head * DKK + cc) * NB + m0 + tb * 4;
            *(uint2*)&g_Vth[o] = make_uint2(u0, u1);
        }
    } else if (mat == 0) {
#pragma unroll
        for (int nt = 0; nt < 16; nt++)
#pragma unroll
            for (int hf = 0; hf < 2; hf++) {
                int row = m0 + er + hf * 8;
                int col = nb + nt * 8 + tcol;
                int head = col >> 6, cc = col & 63;
                float x0 = oacc[nt][2 * hf] * 0.125f;
                float x1 = oacc[nt][2 * hf + 1] * 0.125f;
                unsigned hi, lo;
                cvt_pack_h(x0, x1, hi, lo);
                size_t o = (size_t)(head * NA + row) * DKK + cc;
                *(unsigned*)&g_Qhi[o] = hi;
                *(unsigned*)&g_Qlo[o] = lo;
            }
    } else {
#pragma unroll
        for (int nt = 0; nt < 16; nt++)
#pragma unroll
            for (int hf = 0; hf < 2; hf++) {
                int row = m0 + er + hf * 8;
                int col = nb + nt * 8 + tcol;
                int head = col >> 6, cc = col & 63;
                unsigned u = pack_h(oacc[nt][2 * hf], oacc[nt][2 * hf + 1]);
                size_t o = (size_t)(head * NA + row) * DKK + cc;
                *(unsigned*)&g_Kh[o] = u;
            }
    }
}

// ---------------- attention smem layout: BM=64, 2-stage, fp16 wm ----------------
#define WMB 144                              // wm row pitch bytes (128 data + 16 pad)
#define OFF_Q 0                              // QHI 8192 + QLO 8192
#define OFF_KS(s)  (16384 + (s) * 8192)      // ends 32768
#define OFF_VS(s)  (32768 + (s) * 8192)      // ends 49152
#define OFF_WMS(s) (49152 + (s) * 9216)      // ends 67584
#define OFF_OC 16384      // O-combine 64x64 f32 = 16KB (reuses K stages)
#define OFF_LS 0          // lsum combine 2x64 f32 (reuses Q region)
#define SMEM_BYTES 67584

__device__ __forceinline__ void load_tiles(uint32_t smb, int tid, int h, int a0, int bt) {
    const int s = bt & 1, b0 = bt * BC;
    for (int i = tid; i < 512; i += 256) {          // K + V: 64 rows x 8 chunks
        int r = i >> 3, c = i & 7;
        uint32_t sw = sw128(r * 128 + c * 16);
        CP_ASYNC16(smb + OFF_KS(s) + sw,
                   (const char*)&g_Kh[((size_t)h * NB + b0 + r) * DKK] + c * 16);
        CP_ASYNC16(smb + OFF_VS(s) + sw,
                   (const char*)&g_Vth[((size_t)(h * DKK + r)) * NB + b0] + c * 16);
    }
    for (int i = tid; i < 512; i += 256) {          // wm fp16: 64 rows x 128B
        int r = i >> 3, c = i & 7;
        CP_ASYNC16(smb + OFF_WMS(s) + r * WMB + c * 16,
                   (const char*)&g_wm[(size_t)(a0 + r) * NB + b0] + c * 16);
    }
}

// ---------------- attention mainloop: 256 threads, 2 CTAs/SM, P single-fp16 ----------------
__global__ void __launch_bounds__(256, 2) attn_kernel() {
    extern __shared__ char sm[];
    const uint32_t smb = smem_u32(sm);
    const int tid = threadIdx.x, wid = tid >> 5, lane = tid & 31;
    const int wg = wid >> 2, wrow = wid & 3;
    const int a0 = blockIdx.x * BMA, h = blockIdx.y;

    for (int i = tid; i < 512; i += 256) {          // Q: 64 rows x 8 chunks, hi+lo
        int r = i >> 3, c = i & 7;
        uint32_t sw = sw128(r * 128 + c * 16);
        CP_ASYNC16(smb + OFF_Q + sw,
                   (const char*)&g_Qhi[((size_t)h * NA + a0 + r) * DKK] + c * 16);
        CP_ASYNC16(smb + OFF_Q + 8192 + sw,
                   (const char*)&g_Qlo[((size_t)h * NA + a0 + r) * DKK] + c * 16);
    }
    CP_COMMIT();
    load_tiles(smb, tid, h, a0, 0); CP_COMMIT();
    load_tiles(smb, tid, h, a0, 1); CP_COMMIT();

    float oacc[8][4];
#pragma unroll
    for (int nt = 0; nt < 8; nt++)
#pragma unroll
        for (int e = 0; e < 4; e++) oacc[nt][e] = 0.f;
    float lsum0 = 0.f, lsum1 = 0.f;

    const int qrow = wrow * 16 + (lane & 15);
    const int qcb = (lane >> 4) * 16;
    const int brow = (lane & 7) + ((lane >> 4) << 3);
    const int bkb = ((lane >> 3) & 1) * 16;
    const int er = wrow * 16 + (lane >> 2);
    const int tcol = (lane & 3) * 2;

    CP_WAITG(2);
    __syncthreads();

    for (int bt = 0; bt < NT; bt++) {
        const int s = bt & 1;
        CP_WAITG(1);
        __syncthreads();

        // ---- S(wg half) = Q K^T : (qh+ql)·kh ----
        float sacc[4][4];
#pragma unroll
        for (int nt = 0; nt < 4; nt++)
#pragma unroll
            for (int e = 0; e < 4; e++) sacc[nt][e] = 0.f;

        const uint32_t kbase = smb + OFF_KS(s);
#pragma unroll
        for (int kc = 0; kc < 4; kc++) {
            unsigned qh[4], ql[4];
            uint32_t qsw = sw128(qrow * 128 + kc * 32 + qcb);
            LDSM4(qh[0], qh[1], qh[2], qh[3], smb + OFF_Q + qsw);
            LDSM4(ql[0], ql[1], ql[2], ql[3], smb + OFF_Q + 8192 + qsw);
#pragma unroll
            for (int ngl = 0; ngl < 2; ngl++) {
                const int ng = wg * 2 + ngl;
                unsigned bh[4];
                uint32_t sw = sw128((ng * 16 + brow) * 128 + kc * 32 + bkb);
                LDSM4(bh[0], bh[1], bh[2], bh[3], kbase + sw);
                mma_f16(sacc[2 * ngl], qh, &bh[0]);
                mma_f16(sacc[2 * ngl + 1], qh, &bh[2]);
                mma_f16(sacc[2 * ngl], ql, &bh[0]);
                mma_f16(sacc[2 * ngl + 1], ql, &bh[2]);
            }
        }

        // ---- softmax epilogue (fp16 wm), P packed single fp16 ----
        unsigned pH[2][4];
        const char* wmp = sm + OFF_WMS(s) + er * WMB + (wg * 32 + tcol) * 2;
#pragma unroll
        for (int nt = 0; nt < 4; nt++) {
            float2 w0 = __half22float2(*(const __half2*)(wmp + nt * 16));
            float2 w1 = __half22float2(*(const __half2*)(wmp + 8 * WMB + nt * 16));
            float t00 = fminf(fmaxf(sacc[nt][0] + w0.x, -10.f), 10.f);
            float t01 = fminf(fmaxf(sacc[nt][1] + w0.y, -10.f), 10.f);
            float t10 = fminf(fmaxf(sacc[nt][2] + w1.x, -10.f), 10.f);
            float t11 = fminf(fmaxf(sacc[nt][3] + w1.y, -10.f), 10.f);
            float p00 = __expf(t00 - 10.f), p01 = __expf(t01 - 10.f);
            float p10 = __expf(t10 - 10.f), p11 = __expf(t11 - 10.f);
            lsum0 += p00 + p01;
            lsum1 += p10 + p11;
            int kt = nt >> 1, j = (nt & 1) * 2;
            pH[kt][j] = pack_h(p00, p01);
            pH[kt][j + 1] = pack_h(p10, p11);
        }

        // ---- O += P(wg half) V(wg keys) : single-term ----
        const uint32_t vbase = smb + OFF_VS(s);
#pragma unroll
        for (int ktl = 0; ktl < 2; ktl++) {
            const int kt = wg * 2 + ktl;
#pragma unroll
            for (int ng = 0; ng < 4; ng++) {
                unsigned bh[4];
                uint32_t sw = sw128((ng * 16 + brow) * 128 + kt * 32 + bkb);
                LDSM4(bh[0], bh[1], bh[2], bh[3], vbase + sw);
                mma_f16(oacc[2 * ng], pH[ktl], &bh[0]);
                mma_f16(oacc[2 * ng + 1], pH[ktl], &bh[2]);
            }
        }

        __syncthreads();
        if (bt + 2 < NT) load_tiles(smb, tid, h, a0, bt + 2);
        CP_COMMIT();
    }

    // ---- combine the two warpgroup halves ----
    lsum0 += __shfl_xor_sync(0xFFFFFFFFu, lsum0, 1);
    lsum0 += __shfl_xor_sync(0xFFFFFFFFu, lsum0, 2);
    lsum1 += __shfl_xor_sync(0xFFFFFFFFu, lsum1, 1);
    lsum1 += __shfl_xor_sync(0xFFFFFFFFu, lsum1, 2);

    float* sls = (float*)(sm + OFF_LS);
    float* soc = (float*)(sm + OFF_OC);
    if ((lane & 3) == 0) {
        sls[wg * 64 + er] = lsum0;
        sls[wg * 64 + er + 8] = lsum1;
    }
    if (wg == 1) {
#pragma unroll
        for (int ng = 0; ng < 4; ng++)
#pragma unroll
            for (int j = 0; j < 2; j++) {
                int c = ng * 16 + j * 8 + tcol;
                *(float2*)&soc[er * 64 + c] =
                    make_float2(oacc[2 * ng + j][0], oacc[2 * ng + j][1]);
                *(float2*)&soc[(er + 8) * 64 + c] =
                    make_float2(oacc[2 * ng + j][2], oacc[2 * ng + j][3]);
            }
    }
    __syncthreads();
    if (wg == 0) {
        const float inv0 = 0.25f / (sls[er] + sls[64 + er]);
        const float inv1 = 0.25f / (sls[er + 8] + sls[64 + er + 8]);
        float* d0 = &g_ctx[((size_t)h * NA + a0 + er) * DKK + tcol];
        float* d1 = d0 + 8 * DKK;
#pragma unroll
        for (int ng = 0; ng < 4; ng++)
#pragma unroll
            for (int j = 0; j < 2; j++) {
                int c = ng * 16 + j * 8 + tcol;
                float2 u0 = *(float2*)&soc[er * 64 + c];
                float2 u1 = *(float2*)&soc[(er + 8) * 64 + c];
                *(float2*)(d0 + ng * 16 + j * 8) =
                    make_float2((oacc[2 * ng + j][0] + u0.x) * inv0,
                                (oacc[2 * ng + j][1] + u0.y) * inv0);
                *(float2*)(d1 + ng * 16 + j * 8) =
                    make_float2((oacc[2 * ng + j][2] + u1.x) * inv1,
                                (oacc[2 * ng + j][3] + u1.y) * inv1);
            }
    }
}

// ---------------- final reduce ----------------
__global__ void __launch_bounds__(256) reduce_kernel(float* __restrict__ out) {
    int idx = blockIdx.x * 256 + threadIdx.x;
    const int NC = NA * DKK;
    if (idx < NC) {
        out[idx] = g_ctx[idx] + g_ctx[idx + NC] + g_ctx[idx + 2 * NC] + g_ctx[idx + 3 * NC];
    } else if (idx < NC + NA) {
        out[idx] = 1.0f;
    }
}

// ---------------- launch ----------------
extern "C" void kernel_launch(void* const* d_in, const int* in_sizes, int n_in,
                              void* d_out, int out_size)
{
    const float* a_z    = (const float*)d_in[0];
    const float* bv_z   = (const float*)d_in[1];
    const void*  mask   = d_in[2];
    const float* weight = (const float*)d_in[3];
    const float* Wq     = (const float*)d_in[4];
    const float* Wk     = (const float*)d_in[5];
    const float* Wv     = (const float*)d_in[6];
    float* out = (float*)d_out;

    detect_mask_kind<<<1, 1024>>>((const unsigned int*)mask);
    prep_wm<<<8192, 256>>>((const float4*)weight, mask);

    cudaFuncSetAttribute(proj_mma, cudaFuncAttributeMaxDynamicSharedMemorySize, PJ_SMEM);
    proj_mma<<<dim3(NA / 128, 2, 3), 256, PJ_SMEM>>>(a_z, bv_z, Wq, Wk, Wv);

    cudaFuncSetAttribute(attn_kernel, cudaFuncAttributeMaxDynamicSharedMemorySize, SMEM_BYTES);
    attn_kernel<<<dim3(NA / BMA, HH), 256, SMEM_BYTES>>>();

    reduce_kernel<<<(NA * DKK + NA + 255) / 256, 256>>>(out);
}

// round 14
// speedup vs baseline: 1.7951x; 1.0601x over previous
#include <cuda_runtime.h>
#include <cuda_bf16.h>
#include <cuda_fp16.h>
#include <cstdint>

#define NA 4096
#define NB 4096
#define DD 256
#define HH 4
#define DKK 64
#define BMA 64          // attn rows per CTA (2 CTAs/SM)
#define BC 64
#define NT (NB / BC)

// ---------------- device scratch ----------------
__device__ __half g_Qh[HH * NA * DKK];
__device__ __half g_Kh[HH * NB * DKK];
__device__ __half g_Vth[HH * DKK * NB];          // [h][dk][token]
__device__ __half g_wm[(size_t)NA * NB];         // fp16: san(weight) + (mask?0:-1e4)
__device__ float g_ctx[HH * NA * DKK];
__device__ int g_mask_kind;

// ---------------- helpers ----------------
__device__ __forceinline__ uint32_t smem_u32(const void* p) {
    uint32_t a;
    asm("{ .reg .u64 t; cvta.to.shared.u64 t, %1; cvt.u32.u64 %0, t; }" : "=r"(a) : "l"(p));
    return a;
}
__device__ __forceinline__ uint32_t sw128(uint32_t o) { return o ^ ((o >> 3) & 0x70); }

#define CP_ASYNC16(dst, src) \
    asm volatile("cp.async.cg.shared.global [%0], [%1], 16;\n" :: "r"(dst), "l"(src))
#define CP_COMMIT()  asm volatile("cp.async.commit_group;\n" ::: "memory")
#define CP_WAITG(n)  asm volatile("cp.async.wait_group %0;\n" :: "n"(n) : "memory")

#define LDSM4(r0, r1, r2, r3, a) \
    asm volatile("ldmatrix.sync.aligned.m8n8.x4.shared.b16 {%0,%1,%2,%3}, [%4];" \
                 : "=r"(r0), "=r"(r1), "=r"(r2), "=r"(r3) : "r"(a))

__device__ __forceinline__ void mma_f16(float* c, const unsigned* a, const unsigned* b) {
    asm volatile(
        "mma.sync.aligned.m16n8k16.row.col.f32.f16.f16.f32 "
        "{%0,%1,%2,%3}, {%4,%5,%6,%7}, {%8,%9}, {%0,%1,%2,%3};\n"
        : "+f"(c[0]), "+f"(c[1]), "+f"(c[2]), "+f"(c[3])
        : "r"(a[0]), "r"(a[1]), "r"(a[2]), "r"(a[3]), "r"(b[0]), "r"(b[1]));
}

__device__ __forceinline__ void cvt_pack_h(float x0, float x1, unsigned& hi, unsigned& lo) {
    __half h0 = __float2half_rn(x0), h1 = __float2half_rn(x1);
    __half l0 = __float2half_rn(x0 - __half2float(h0));
    __half l1 = __float2half_rn(x1 - __half2float(h1));
    hi = ((unsigned)__half_as_ushort(h1) << 16) | (unsigned)__half_as_ushort(h0);
    lo = ((unsigned)__half_as_ushort(l1) << 16) | (unsigned)__half_as_ushort(l0);
}
__device__ __forceinline__ unsigned pack_h(float x0, float x1) {
    return ((unsigned)__half_as_ushort(__float2half_rn(x1)) << 16)
         | (unsigned)__half_as_ushort(__float2half_rn(x0));
}

__device__ __forceinline__ float san(float x) {
    if (isnan(x)) return 0.f;
    if (isinf(x)) return x > 0.f ? 1.f : -1.f;
    return x;
}

// ---------------- mask dtype detector ----------------
__global__ void detect_mask_kind(const unsigned int* __restrict__ m) {
    __shared__ int s_i32, s_f32;
    if (threadIdx.x == 0) { s_i32 = 1; s_f32 = 1; }
    __syncthreads();
    int ok_i = 1, ok_f = 1;
    for (int i = threadIdx.x; i < 4096; i += 1024) {
        unsigned v = m[i];
        ok_i &= (v <= 1u);
        ok_f &= (v == 0u || v == 0x3F800000u);
    }
    if (!ok_i) atomicAnd(&s_i32, 0);
    if (!ok_f) atomicAnd(&s_f32, 0);
    __syncthreads();
    if (threadIdx.x == 0) g_mask_kind = s_i32 ? 1 : (s_f32 ? 2 : 0);
}

// ---------------- prep: fold sanitize + mask into fp16 weight ----------------
__global__ void __launch_bounds__(256) prep_wm(const float4* __restrict__ w4,
                                               const void* __restrict__ mraw) {
    const int kind = g_mask_kind;
    const size_t n4 = (size_t)NA * NB / 4;
    size_t i = (size_t)blockIdx.x * 256 + threadIdx.x;
    const size_t stride = (size_t)gridDim.x * 256;
    for (; i < n4; i += stride) {
        float4 w = w4[i];
        w.x = san(w.x); w.y = san(w.y); w.z = san(w.z); w.w = san(w.w);
        int b0, b1, b2, b3;
        if (kind == 1) {
            int4 m = ((const int4*)mraw)[i];
            b0 = m.x != 0; b1 = m.y != 0; b2 = m.z != 0; b3 = m.w != 0;
        } else if (kind == 2) {
            float4 m = ((const float4*)mraw)[i];
            b0 = m.x != 0.f; b1 = m.y != 0.f; b2 = m.z != 0.f; b3 = m.w != 0.f;
        } else {
            uchar4 m = ((const uchar4*)mraw)[i];
            b0 = m.x != 0; b1 = m.y != 0; b2 = m.z != 0; b3 = m.w != 0;
        }
        float ox = w.x + (b0 ? 0.f : -10000.f);
        float oy = w.y + (b1 ? 0.f : -10000.f);
        float oz = w.z + (b2 ? 0.f : -10000.f);
        float ow = w.w + (b3 ? 0.f : -10000.f);
        uint2 pk = make_uint2(pack_h(ox, oy), pack_h(oz, ow));
        *(uint2*)&g_wm[i * 4] = pk;
    }
}

// ---------------- projections: fp16 2-term (X hi/lo, W single); Q stored single ----------------
#define PJ_XF(s)  ((s) * 32768)
#define PJ_WF(s)  (65536 + (s) * 32768)
#define PJ_XHI 131072
#define PJ_XLO 147456
#define PJ_WH  163840
#define PJ_SMEM 180224
#define VT_PITCH 132

__global__ void __launch_bounds__(256, 1) proj_mma(
    const float* __restrict__ a_z, const float* __restrict__ bv_z,
    const float* __restrict__ Wq, const float* __restrict__ Wk, const float* __restrict__ Wv)
{
    extern __shared__ char sm[];
    const uint32_t smb = smem_u32(sm);
    const int tid = threadIdx.x, wid = tid >> 5, lane = tid & 31;
    const int mat = blockIdx.z;
    const int m0 = blockIdx.x * 128, nb = blockIdx.y * 128;
    const float* X = (mat == 0) ? a_z : bv_z;
    const float* W = (mat == 0) ? Wq : (mat == 1 ? Wk : Wv);

    auto load_chunk = [&](int c) {
        const int s = c & 1;
        for (int i = tid; i < 2048; i += 256) {
            int r = i >> 4, q = i & 15;
            CP_ASYNC16(smb + PJ_XF(s) + r * 256 + q * 16,
                       (const char*)&X[(size_t)(m0 + r) * DD + c * 64] + q * 16);
            CP_ASYNC16(smb + PJ_WF(s) + r * 256 + q * 16,
                       (const char*)&W[(size_t)(nb + r) * DD + c * 64] + q * 16);
        }
    };
    load_chunk(0); CP_COMMIT();
    load_chunk(1); CP_COMMIT();

    float oacc[16][4];
#pragma unroll
    for (int nt = 0; nt < 16; nt++)
#pragma unroll
        for (int e = 0; e < 4; e++) oacc[nt][e] = 0.f;

    const int arow = wid * 16 + (lane & 15);
    const int akb = (lane >> 4) * 16;
    const int brow = (lane & 7) + ((lane >> 4) << 3);
    const int bkb = ((lane >> 3) & 1) * 16;

    for (int c = 0; c < 4; c++) {
        const int s = c & 1;
        CP_WAITG(1);
        __syncthreads();
#pragma unroll
        for (int j = 0; j < 16; j++) {
            int p = tid + j * 256;
            int r = p >> 5, cp2 = p & 31;
            float2 xv = *(const float2*)(sm + PJ_XF(s) + r * 256 + cp2 * 8);
            float2 wv = *(const float2*)(sm + PJ_WF(s) + r * 256 + cp2 * 8);
            unsigned hi, lo;
            cvt_pack_h(san(xv.x), san(xv.y), hi, lo);
            uint32_t off = sw128(r * 128 + cp2 * 4);
            *(uint32_t*)(sm + PJ_XHI + off) = hi;
            *(uint32_t*)(sm + PJ_XLO + off) = lo;
            *(uint32_t*)(sm + PJ_WH + off) = pack_h(wv.x, wv.y);
        }
        __syncthreads();
#pragma unroll
        for (int kc = 0; kc < 4; kc++) {
            unsigned ah[4], al[4];
            uint32_t asw = sw128(arow * 128 + kc * 32 + akb);
            LDSM4(ah[0], ah[1], ah[2], ah[3], smb + PJ_XHI + asw);
            LDSM4(al[0], al[1], al[2], al[3], smb + PJ_XLO + asw);
#pragma unroll
            for (int ng = 0; ng < 8; ng++) {
                unsigned bh[4];
                uint32_t bsw = sw128((ng * 16 + brow) * 128 + kc * 32 + bkb);
                LDSM4(bh[0], bh[1], bh[2], bh[3], smb + PJ_WH + bsw);
                mma_f16(oacc[2 * ng], ah, &bh[0]);
                mma_f16(oacc[2 * ng + 1], ah, &bh[2]);
                mma_f16(oacc[2 * ng], al, &bh[0]);
                mma_f16(oacc[2 * ng + 1], al, &bh[2]);
            }
        }
        __syncthreads();
        if (c + 2 < 4) load_chunk(c + 2);
        CP_COMMIT();
    }

    const int er = wid * 16 + (lane >> 2);
    const int tcol = (lane & 3) * 2;

    if (mat == 2) {
        float* smf = (float*)sm;
#pragma unroll
        for (int nt = 0; nt < 16; nt++)
#pragma unroll
            for (int hf = 0; hf < 2; hf++) {
                int row = er + hf * 8;
                int col = nt * 8 + tcol;
                smf[(col) * VT_PITCH + row] = oacc[nt][2 * hf];
                smf[(col + 1) * VT_PITCH + row] = oacc[nt][2 * hf + 1];
            }
        __syncthreads();
        for (int idx = tid; idx < 128 * 32; idx += 256) {
            int c = idx >> 5, tb = idx & 31;
            const float* src = &smf[c * VT_PITCH + tb * 4];
            unsigned u0 = pack_h(src[0], src[1]);
            unsigned u1 = pack_h(src[2], src[3]);
            int col = nb + c;
            int head = col >> 6, cc = col & 63;
            size_t o = (size_t)(head * DKK + cc) * NB + m0 + tb * 4;
            *(uint2*)&g_Vth[o] = make_uint2(u0, u1);
        }
    } else {
        const float scale = (mat == 0) ? 0.125f : 1.0f;
        __half* dst = (mat == 0) ? g_Qh : g_Kh;
#pragma unroll
        for (int nt = 0; nt < 16; nt++)
#pragma unroll
            for (int hf = 0; hf < 2; hf++) {
                int row = m0 + er + hf * 8;
                int col = nb + nt * 8 + tcol;
                int head = col >> 6, cc = col & 63;
                unsigned u = pack_h(oacc[nt][2 * hf] * scale, oacc[nt][2 * hf + 1] * scale);
                size_t o = (size_t)(head * NA + row) * DKK + cc;
                *(unsigned*)&dst[o] = u;
            }
    }
}

// ---------------- attention smem layout: BM=64, 2-stage, all single-fp16 ----------------
#define WMB 144                              // wm row pitch bytes (128 data + 16 pad)
#define OFF_Q 0                              // Q single: 8192
#define OFF_KS(s)  (8192 + (s) * 8192)       // ends 24576
#define OFF_VS(s)  (24576 + (s) * 8192)      // ends 40960
#define OFF_WMS(s) (40960 + (s) * 9216)      // ends 59392
#define OFF_OC 8192       // O-combine 64x64 f32 = 16KB (reuses K stages)
#define OFF_LS 0          // lsum combine 2x64 f32 (reuses Q region)
#define SMEM_BYTES 59392

__device__ __forceinline__ void load_tiles(uint32_t smb, int tid, int h, int a0, int bt) {
    const int s = bt & 1, b0 = bt * BC;
    for (int i = tid; i < 512; i += 256) {          // K + V: 64 rows x 8 chunks
        int r = i >> 3, c = i & 7;
        uint32_t sw = sw128(r * 128 + c * 16);
        CP_ASYNC16(smb + OFF_KS(s) + sw,
                   (const char*)&g_Kh[((size_t)h * NB + b0 + r) * DKK] + c * 16);
        CP_ASYNC16(smb + OFF_VS(s) + sw,
                   (const char*)&g_Vth[((size_t)(h * DKK + r)) * NB + b0] + c * 16);
    }
    for (int i = tid; i < 512; i += 256) {          // wm fp16: 64 rows x 128B
        int r = i >> 3, c = i & 7;
        CP_ASYNC16(smb + OFF_WMS(s) + r * WMB + c * 16,
                   (const char*)&g_wm[(size_t)(a0 + r) * NB + b0] + c * 16);
    }
}

// ---------------- attention mainloop: 256 threads, 2 CTAs/SM, Q/P single-fp16 ----------------
__global__ void __launch_bounds__(256, 2) attn_kernel() {
    extern __shared__ char sm[];
    const uint32_t smb = smem_u32(sm);
    const int tid = threadIdx.x, wid = tid >> 5, lane = tid & 31;
    const int wg = wid >> 2, wrow = wid & 3;
    const int a0 = blockIdx.x * BMA, h = blockIdx.y;

    for (int i = tid; i < 512; i += 256) {          // Q single: 64 rows x 8 chunks
        int r = i >> 3, c = i & 7;
        uint32_t sw = sw128(r * 128 + c * 16);
        CP_ASYNC16(smb + OFF_Q + sw,
                   (const char*)&g_Qh[((size_t)h * NA + a0 + r) * DKK] + c * 16);
    }
    CP_COMMIT();
    load_tiles(smb, tid, h, a0, 0); CP_COMMIT();
    load_tiles(smb, tid, h, a0, 1); CP_COMMIT();

    float oacc[8][4];
#pragma unroll
    for (int nt = 0; nt < 8; nt++)
#pragma unroll
        for (int e = 0; e < 4; e++) oacc[nt][e] = 0.f;
    float lsum0 = 0.f, lsum1 = 0.f;

    const int qrow = wrow * 16 + (lane & 15);
    const int qcb = (lane >> 4) * 16;
    const int brow = (lane & 7) + ((lane >> 4) << 3);
    const int bkb = ((lane >> 3) & 1) * 16;
    const int er = wrow * 16 + (lane >> 2);
    const int tcol = (lane & 3) * 2;

    CP_WAITG(2);
    __syncthreads();

    for (int bt = 0; bt < NT; bt++) {
        const int s = bt & 1;
        CP_WAITG(1);
        __syncthreads();

        // ---- S(wg half) = Q K^T : single-term fp16 ----
        float sacc[4][4];
#pragma unroll
        for (int nt = 0; nt < 4; nt++)
#pragma unroll
            for (int e = 0; e < 4; e++) sacc[nt][e] = 0.f;

        const uint32_t kbase = smb + OFF_KS(s);
#pragma unroll
        for (int kc = 0; kc < 4; kc++) {
            unsigned qh[4];
            uint32_t qsw = sw128(qrow * 128 + kc * 32 + qcb);
            LDSM4(qh[0], qh[1], qh[2], qh[3], smb + OFF_Q + qsw);
#pragma unroll
            for (int ngl = 0; ngl < 2; ngl++) {
                const int ng = wg * 2 + ngl;
                unsigned bh[4];
                uint32_t sw = sw128((ng * 16 + brow) * 128 + kc * 32 + bkb);
                LDSM4(bh[0], bh[1], bh[2], bh[3], kbase + sw);
                mma_f16(sacc[2 * ngl], qh, &bh[0]);
                mma_f16(sacc[2 * ngl + 1], qh, &bh[2]);
            }
        }

        // ---- softmax epilogue (fp16 wm), P packed single fp16 ----
        unsigned pH[2][4];
        const char* wmp = sm + OFF_WMS(s) + er * WMB + (wg * 32 + tcol) * 2;
#pragma unroll
        for (int nt = 0; nt < 4; nt++) {
            float2 w0 = __half22float2(*(const __half2*)(wmp + nt * 16));
            float2 w1 = __half22float2(*(const __half2*)(wmp + 8 * WMB + nt * 16));
            float t00 = fminf(fmaxf(sacc[nt][0] + w0.x, -10.f), 10.f);
            float t01 = fminf(fmaxf(sacc[nt][1] + w0.y, -10.f), 10.f);
            float t10 = fminf(fmaxf(sacc[nt][2] + w1.x, -10.f), 10.f);
            float t11 = fminf(fmaxf(sacc[nt][3] + w1.y, -10.f), 10.f);
            float p00 = __expf(t00 - 10.f), p01 = __expf(t01 - 10.f);
            float p10 = __expf(t10 - 10.f), p11 = __expf(t11 - 10.f);
            lsum0 += p00 + p01;
            lsum1 += p10 + p11;
            int kt = nt >> 1, j = (nt & 1) * 2;
            pH[kt][j] = pack_h(p00, p01);
            pH[kt][j + 1] = pack_h(p10, p11);
        }

        // ---- O += P(wg half) V(wg keys) : single-term ----
        const uint32_t vbase = smb + OFF_VS(s);
#pragma unroll
        for (int ktl = 0; ktl < 2; ktl++) {
            const int kt = wg * 2 + ktl;
#pragma unroll
            for (int ng = 0; ng < 4; ng++) {
                unsigned bh[4];
                uint32_t sw = sw128((ng * 16 + brow) * 128 + kt * 32 + bkb);
                LDSM4(bh[0], bh[1], bh[2], bh[3], vbase + sw);
                mma_f16(oacc[2 * ng], pH[ktl], &bh[0]);
                mma_f16(oacc[2 * ng + 1], pH[ktl], &bh[2]);
            }
        }

        __syncthreads();
        if (bt + 2 < NT) load_tiles(smb, tid, h, a0, bt + 2);
        CP_COMMIT();
    }

    // ---- combine the two warpgroup halves ----
    lsum0 += __shfl_xor_sync(0xFFFFFFFFu, lsum0, 1);
    lsum0 += __shfl_xor_sync(0xFFFFFFFFu, lsum0, 2);
    lsum1 += __shfl_xor_sync(0xFFFFFFFFu, lsum1, 1);
    lsum1 += __shfl_xor_sync(0xFFFFFFFFu, lsum1, 2);

    float* sls = (float*)(sm + OFF_LS);
    float* soc = (float*)(sm + OFF_OC);
    if ((lane & 3) == 0) {
        sls[wg * 64 + er] = lsum0;
        sls[wg * 64 + er + 8] = lsum1;
    }
    if (wg == 1) {
#pragma unroll
        for (int ng = 0; ng < 4; ng++)
#pragma unroll
            for (int j = 0; j < 2; j++) {
                int c = ng * 16 + j * 8 + tcol;
                *(float2*)&soc[er * 64 + c] =
                    make_float2(oacc[2 * ng + j][0], oacc[2 * ng + j][1]);
                *(float2*)&soc[(er + 8) * 64 + c] =
                    make_float2(oacc[2 * ng + j][2], oacc[2 * ng + j][3]);
            }
    }
    __syncthreads();
    if (wg == 0) {
        const float inv0 = 0.25f / (sls[er] + sls[64 + er]);
        const float inv1 = 0.25f / (sls[er + 8] + sls[64 + er + 8]);
        float* d0 = &g_ctx[((size_t)h * NA + a0 + er) * DKK + tcol];
        float* d1 = d0 + 8 * DKK;
#pragma unroll
        for (int ng = 0; ng < 4; ng++)
#pragma unroll
            for (int j = 0; j < 2; j++) {
                int c = ng * 16 + j * 8 + tcol;
                float2 u0 = *(float2*)&soc[er * 64 + c];
                float2 u1 = *(float2*)&soc[(er + 8) * 64 + c];
                *(float2*)(d0 + ng * 16 + j * 8) =
                    make_float2((oacc[2 * ng + j][0] + u0.x) * inv0,
                                (oacc[2 * ng + j][1] + u0.y) * inv0);
                *(float2*)(d1 + ng * 16 + j * 8) =
                    make_float2((oacc[2 * ng + j][2] + u1.x) * inv1,
                                (oacc[2 * ng + j][3] + u1.y) * inv1);
            }
    }
}

// ---------------- final reduce ----------------
__global__ void __launch_bounds__(256) reduce_kernel(float* __restrict__ out) {
    int idx = blockIdx.x * 256 + threadIdx.x;
    const int NC = NA * DKK;
    if (idx < NC) {
        out[idx] = g_ctx[idx] + g_ctx[idx + NC] + g_ctx[idx + 2 * NC] + g_ctx[idx + 3 * NC];
    } else if (idx < NC + NA) {
        out[idx] = 1.0f;
    }
}

// ---------------- launch ----------------
extern "C" void kernel_launch(void* const* d_in, const int* in_sizes, int n_in,
                              void* d_out, int out_size)
{
    const float* a_z    = (const float*)d_in[0];
    const float* bv_z   = (const float*)d_in[1];
    const void*  mask   = d_in[2];
    const float* weight = (const float*)d_in[3];
    const float* Wq     = (const float*)d_in[4];
    const float* Wk     = (const float*)d_in[5];
    const float* Wv     = (const float*)d_in[6];
    float* out = (float*)d_out;

    detect_mask_kind<<<1, 1024>>>((const unsigned int*)mask);
    prep_wm<<<8192, 256>>>((const float4*)weight, mask);

    cudaFuncSetAttribute(proj_mma, cudaFuncAttributeMaxDynamicSharedMemorySize, PJ_SMEM);
    proj_mma<<<dim3(NA / 128, 2, 3), 256, PJ_SMEM>>>(a_z, bv_z, Wq, Wk, Wv);

    cudaFuncSetAttribute(attn_kernel, cudaFuncAttributeMaxDynamicSharedMemorySize, SMEM_BYTES);
    attn_kernel<<<dim3(NA / BMA, HH), 256, SMEM_BYTES>>>();

    reduce_kernel<<<(NA * DKK + NA + 255) / 256, 256>>>(out);
}